// round 2
// baseline (speedup 1.0000x reference)
#include <cuda_runtime.h>
#include <math.h>
#include <stdint.h>

// ---------------- static problem sizes ----------------
#define CC    768
#define D0    16
#define H0    32
#define W0    32
#define NQ    16384      // D0*H0*W0
#define NDQ   2048       // dst tokens (q-level)
#define NAQ   14336      // src tokens (q-level)
#define RQ    8192       // merged srcs
#define UQ    6144       // unmerged srcs
#define MQ    8192       // q tokens after merge (UQ+NDQ)
#define N2    2048       // conv output tokens (8*16*16)
#define NDK   256
#define NAK   1792
#define RK    1024
#define UK    768
#define MK    1024       // kv tokens after merge
#define HEADS 8
#define HD    96

// ---------------- device scratch (static: no allocations allowed) ----------------
__device__ float g_bt[8 * CC * CC];          // transposed conv weights per tap
__device__ float g_xk[N2 * CC];              // conv out -> LN'd (in place)
__device__ float g_mnq[NQ * CC];             // normalized metric (q side)
__device__ float g_mnk[N2 * CC];             // normalized metric (kv side)
__device__ unsigned long long g_keyq[NAQ];
__device__ unsigned long long g_keyk[NAK];
__device__ float g_nvq[NAQ];
__device__ float g_nvk[NAK];
__device__ int g_permq[NAQ];
__device__ int g_permk[NAK];
__device__ int g_dstq[RQ];
__device__ int g_dstk[RK];
__device__ int g_cntq[NDQ];
__device__ int g_cntk[NDK];
__device__ int g_aq[NAQ];
__device__ int g_bq[NDQ];
__device__ int g_ak[NAK];
__device__ int g_bk[NDK];
__device__ float g_xq[MQ * CC];
__device__ float g_xkm[MK * CC];
__device__ float g_qm[MQ * CC];
__device__ float g_kvm[MK * 2 * CC];
__device__ float g_S[MQ * MK];               // per-head scores (reused across heads)
__device__ float g_ao[MQ * CC];
__device__ float g_proj[MQ * CC];

// ---------------- small utility kernels ----------------
__global__ void set_u64_kernel(unsigned long long* p, int n) {
    int i = blockIdx.x * 256 + threadIdx.x;
    if (i < n) p[i] = 0ull;
}
__global__ void set_int_kernel(int* p, int n, int v) {
    int i = blockIdx.x * 256 + threadIdx.x;
    if (i < n) p[i] = v;
}

// b_idx[rank] = token with all-even coords (row-major among such); a_idx likewise for the rest.
__global__ void build_idx_kernel(int D, int H, int W, int* a_idx, int* b_idx) {
    int n = D * H * W;
    int t = blockIdx.x * 256 + threadIdx.x;
    if (t >= n) return;
    int z = t / (H * W), y = (t / W) % H, xx = t % W;
    int hw2 = (H >> 1) * (W >> 1);
    if (((z | y | xx) & 1) == 0) {
        b_idx[(z >> 1) * hw2 + (y >> 1) * (W >> 1) + (xx >> 1)] = t;
    } else {
        int cez = (z + 1) >> 1, cey = (y + 1) >> 1, cex = (xx + 1) >> 1;
        int before = cez * hw2;
        if ((z & 1) == 0) { before += cey * (W >> 1); if ((y & 1) == 0) before += cex; }
        a_idx[t - before] = t;
    }
}

// bt[kk][o][c] = w[o][c][kk]   (w layout: o*6144 + c*8 + kk)
__global__ void transpose_w_kernel(const float* __restrict__ w, float* __restrict__ bt) {
    int i = blockIdx.x * 256 + threadIdx.x;
    if (i >= 8 * CC * CC) return;
    int kk = i / (CC * CC);
    int rem = i - kk * (CC * CC);
    int o = rem / CC, c = rem - o * CC;
    bt[i] = w[o * (CC * 8) + c * 8 + kk];
}

// ---------------- conv3d (stride2 VALID) as 8-tap accumulated GEMM ----------------
__global__ void __launch_bounds__(256) conv_kernel(
    const float* __restrict__ x, const float* __restrict__ bt,
    const float* __restrict__ bias, float* __restrict__ out)
{
    __shared__ float As[16][68];
    __shared__ float Bs[16][68];
    const int tid = threadIdx.x;
    const int tx = tid & 15, ty = tid >> 4;
    const int m0 = blockIdx.y * 64, n0 = blockIdx.x * 64;
    const int lr = tid >> 2, lc = (tid & 3) << 2;
    const int m = m0 + lr;
    const int z2 = m >> 8, y2 = (m >> 4) & 15, x2 = m & 15;
    float acc[4][4];
#pragma unroll
    for (int i = 0; i < 4; i++)
#pragma unroll
        for (int j = 0; j < 4; j++) acc[i][j] = 0.f;

    for (int kkk = 0; kkk < 8; kkk++) {
        const int kz = kkk >> 2, ky = (kkk >> 1) & 1, kx = kkk & 1;
        const int tok = (2 * z2 + kz) * (H0 * W0) + (2 * y2 + ky) * W0 + (2 * x2 + kx);
        const float* Arow = x + tok * CC;
        const float* Brow = bt + kkk * (CC * CC) + (n0 + lr) * CC;
        for (int k0 = 0; k0 < CC; k0 += 16) {
            float4 av = *reinterpret_cast<const float4*>(Arow + k0 + lc);
            float4 bv = *reinterpret_cast<const float4*>(Brow + k0 + lc);
            As[lc + 0][lr] = av.x; As[lc + 1][lr] = av.y; As[lc + 2][lr] = av.z; As[lc + 3][lr] = av.w;
            Bs[lc + 0][lr] = bv.x; Bs[lc + 1][lr] = bv.y; Bs[lc + 2][lr] = bv.z; Bs[lc + 3][lr] = bv.w;
            __syncthreads();
#pragma unroll
            for (int kk = 0; kk < 16; kk++) {
                float4 a4 = *reinterpret_cast<const float4*>(&As[kk][ty << 2]);
                float4 b4 = *reinterpret_cast<const float4*>(&Bs[kk][tx << 2]);
                float ar[4] = {a4.x, a4.y, a4.z, a4.w};
                float br[4] = {b4.x, b4.y, b4.z, b4.w};
#pragma unroll
                for (int i = 0; i < 4; i++)
#pragma unroll
                    for (int j = 0; j < 4; j++)
                        acc[i][j] = fmaf(ar[i], br[j], acc[i][j]);
            }
            __syncthreads();
        }
    }
#pragma unroll
    for (int i = 0; i < 4; i++) {
        int row = m0 + (ty << 2) + i;
#pragma unroll
        for (int j = 0; j < 4; j++) {
            int col = n0 + (tx << 2) + j;
            out[row * CC + col] = acc[i][j] + bias[col];
        }
    }
}

// ---------------- LayerNorm (in place, per row of 768) ----------------
__global__ void __launch_bounds__(256) ln_kernel(float* __restrict__ xk,
    const float* __restrict__ g, const float* __restrict__ b)
{
    int row = blockIdx.x;
    float* p = xk + row * CC;
    __shared__ float red[256];
    int tid = threadIdx.x;
    float s = 0.f;
    for (int c = tid; c < CC; c += 256) s += p[c];
    red[tid] = s; __syncthreads();
    for (int off = 128; off; off >>= 1) { if (tid < off) red[tid] += red[tid + off]; __syncthreads(); }
    float mean = red[0] / (float)CC;
    __syncthreads();
    float v = 0.f;
    for (int c = tid; c < CC; c += 256) { float d = p[c] - mean; v += d * d; }
    red[tid] = v; __syncthreads();
    for (int off = 128; off; off >>= 1) { if (tid < off) red[tid] += red[tid + off]; __syncthreads(); }
    float var = red[0] / (float)CC;
    float inv = (float)(1.0 / sqrt((double)var + 1e-5));
    __syncthreads();
    for (int c = tid; c < CC; c += 256) p[c] = (p[c] - mean) * inv * g[c] + b[c];
}

// ---------------- row L2-normalize ----------------
__global__ void __launch_bounds__(256) rownorm_kernel(const float* __restrict__ src, float* __restrict__ dst) {
    int row = blockIdx.x;
    const float* p = src + row * CC;
    float* q = dst + row * CC;
    __shared__ float red[256];
    int tid = threadIdx.x;
    float s = 0.f;
    for (int c = tid; c < CC; c += 256) { float v = p[c]; s += v * v; }
    red[tid] = s; __syncthreads();
    for (int off = 128; off; off >>= 1) { if (tid < off) red[tid] += red[tid + off]; __syncthreads(); }
    float inv = (float)(1.0 / sqrt((double)red[0]));
    for (int c = tid; c < CC; c += 256) q[c] = p[c] * inv;
}

// ---------------- fused cosine-score GEMM + per-src argmax ----------------
// key[src] = max over dst of ((orderedFloat(score)<<32) | ~dst)  => first-max tie break
__global__ void __launch_bounds__(256) score_max_kernel(
    const float* __restrict__ mn,
    const int* __restrict__ a_idx, const int* __restrict__ b_idx,
    unsigned long long* __restrict__ key)
{
    __shared__ float As[16][68];
    __shared__ float Bs[16][68];
    __shared__ unsigned long long red[64];
    const int tid = threadIdx.x;
    const int tx = tid & 15, ty = tid >> 4;
    const int m0 = blockIdx.y * 64, n0 = blockIdx.x * 64;
    const int lr = tid >> 2, lc = (tid & 3) << 2;
    const int arow = a_idx[m0 + lr];
    const int brow = b_idx[n0 + lr];
    if (tid < 64) red[tid] = 0ull;
    float acc[4][4];
#pragma unroll
    for (int i = 0; i < 4; i++)
#pragma unroll
        for (int j = 0; j < 4; j++) acc[i][j] = 0.f;

    for (int k0 = 0; k0 < CC; k0 += 16) {
        float4 av = *reinterpret_cast<const float4*>(mn + arow * CC + k0 + lc);
        float4 bv = *reinterpret_cast<const float4*>(mn + brow * CC + k0 + lc);
        As[lc + 0][lr] = av.x; As[lc + 1][lr] = av.y; As[lc + 2][lr] = av.z; As[lc + 3][lr] = av.w;
        Bs[lc + 0][lr] = bv.x; Bs[lc + 1][lr] = bv.y; Bs[lc + 2][lr] = bv.z; Bs[lc + 3][lr] = bv.w;
        __syncthreads();
#pragma unroll
        for (int kk = 0; kk < 16; kk++) {
            float4 a4 = *reinterpret_cast<const float4*>(&As[kk][ty << 2]);
            float4 b4 = *reinterpret_cast<const float4*>(&Bs[kk][tx << 2]);
            float ar[4] = {a4.x, a4.y, a4.z, a4.w};
            float br[4] = {b4.x, b4.y, b4.z, b4.w};
#pragma unroll
            for (int i = 0; i < 4; i++)
#pragma unroll
                for (int j = 0; j < 4; j++)
                    acc[i][j] = fmaf(ar[i], br[j], acc[i][j]);
        }
        __syncthreads();
    }
#pragma unroll
    for (int i = 0; i < 4; i++) {
        unsigned long long best = 0ull;
#pragma unroll
        for (int j = 0; j < 4; j++) {
            int col = n0 + (tx << 2) + j;
            unsigned u = __float_as_uint(acc[i][j]);
            unsigned o = (u & 0x80000000u) ? ~u : (u | 0x80000000u);
            unsigned long long k = ((unsigned long long)o << 32) | (unsigned)(~col);
            if (k > best) best = k;
        }
        atomicMax(&red[(ty << 2) + i], best);
    }
    __syncthreads();
    if (tid < 64) atomicMax(&key[m0 + tid], red[tid]);
}

__global__ void unpack_val_kernel(const unsigned long long* __restrict__ key, float* __restrict__ val, int n) {
    int i = blockIdx.x * 256 + threadIdx.x;
    if (i >= n) return;
    unsigned o = (unsigned)(key[i] >> 32);
    unsigned u = (o & 0x80000000u) ? (o ^ 0x80000000u) : ~o;
    val[i] = __uint_as_float(u);
}

// Stable descending rank by counting: rank = #{v_j > v_i} + #{j<i : v_j == v_i}; perm[rank]=i
__global__ void __launch_bounds__(256) rank_kernel(const float* __restrict__ v, int* __restrict__ perm, int n) {
    int i = blockIdx.x * 256 + threadIdx.x;
    float vi = (i < n) ? v[i] : 0.f;
    int r = 0;
    __shared__ float sv[256];
    for (int base = 0; base < n; base += 256) {
        int j = base + threadIdx.x;
        sv[threadIdx.x] = (j < n) ? v[j] : -3.4e38f;
        __syncthreads();
        int lim = min(256, n - base);
        for (int t = 0; t < lim; t++) {
            float vj = sv[t];
            int j2 = base + t;
            if (vj > vi || (vj == vi && j2 < i)) r++;
        }
        __syncthreads();
    }
    if (i < n) perm[r] = i;
}

__global__ void fill_dst_kernel(const int* __restrict__ perm, const unsigned long long* __restrict__ key,
                                int* __restrict__ dst, int* __restrict__ cnt, int R) {
    int e = blockIdx.x * 256 + threadIdx.x;
    if (e >= R) return;
    int s = perm[e];
    unsigned low = (unsigned)(key[s]);
    int dd = (int)(~low);
    dst[e] = dd;
    atomicAdd(&cnt[dd], 1);
}

__global__ void __launch_bounds__(256) merge_gather_kernel(const float* __restrict__ src, float* __restrict__ buf,
    const int* __restrict__ a_idx, const int* __restrict__ b_idx,
    const int* __restrict__ perm, int U, int R)
{
    int row = blockIdx.x;
    int tok = (row < U) ? a_idx[perm[R + row]] : b_idx[row - U];
    const float* s = src + tok * CC;
    float* d = buf + row * CC;
    for (int c = threadIdx.x; c < CC; c += 256) d[c] = s[c];
}

__global__ void __launch_bounds__(256) scatter_add_kernel(const float* __restrict__ src, float* __restrict__ buf,
    const int* __restrict__ a_idx, const int* __restrict__ perm, const int* __restrict__ dst, int U)
{
    int e = blockIdx.x;
    int tok = a_idx[perm[e]];
    float* d = buf + (U + dst[e]) * CC;
    const float* s = src + tok * CC;
    for (int c = threadIdx.x; c < CC; c += 256) atomicAdd(&d[c], s[c]);
}

__global__ void __launch_bounds__(256) div_cnt_kernel(float* __restrict__ buf, const int* __restrict__ cnt, int U) {
    int dr = blockIdx.x;
    float cf = (float)cnt[dr];
    float* p = buf + (U + dr) * CC;
    for (int c = threadIdx.x; c < CC; c += 256) p[c] = p[c] / cf;
}

// ---------------- generic 64x64 SGEMM: C = scale*A@op(B) (+bias) ----------------
// TRANSB=true : B is (N,K) row-major (compute A@B^T)
// TRANSB=false: B is (K,N) row-major (compute A@B)
template <bool TRANSB>
__global__ void __launch_bounds__(256) gemm64_kernel(
    const float* __restrict__ A, int lda,
    const float* __restrict__ B, int ldb,
    float* __restrict__ C, int ldc,
    const float* __restrict__ bias, float scale,
    int M, int N, int K)
{
    __shared__ float As[16][68];
    __shared__ float Bs[16][68];
    const int tid = threadIdx.x;
    const int tx = tid & 15, ty = tid >> 4;
    const int m0 = blockIdx.y * 64, n0 = blockIdx.x * 64;
    const int lr = tid >> 2, lc = (tid & 3) << 2;
    const int br = tid >> 4, bc = (tid & 15) << 2;
    float acc[4][4];
#pragma unroll
    for (int i = 0; i < 4; i++)
#pragma unroll
        for (int j = 0; j < 4; j++) acc[i][j] = 0.f;

    for (int k0 = 0; k0 < K; k0 += 16) {
        float4 av = *reinterpret_cast<const float4*>(A + (m0 + lr) * lda + k0 + lc);
        As[lc + 0][lr] = av.x; As[lc + 1][lr] = av.y; As[lc + 2][lr] = av.z; As[lc + 3][lr] = av.w;
        if (TRANSB) {
            float4 bv;
            if (n0 + lr < N) bv = *reinterpret_cast<const float4*>(B + (n0 + lr) * ldb + k0 + lc);
            else bv = make_float4(0.f, 0.f, 0.f, 0.f);
            Bs[lc + 0][lr] = bv.x; Bs[lc + 1][lr] = bv.y; Bs[lc + 2][lr] = bv.z; Bs[lc + 3][lr] = bv.w;
        } else {
            const float* Bp = B + (k0 + br) * ldb + n0;
#pragma unroll
            for (int j = 0; j < 4; j++)
                Bs[br][bc + j] = (n0 + bc + j < N) ? Bp[bc + j] : 0.f;
        }
        __syncthreads();
#pragma unroll
        for (int kk = 0; kk < 16; kk++) {
            float4 a4 = *reinterpret_cast<const float4*>(&As[kk][ty << 2]);
            float4 b4 = *reinterpret_cast<const float4*>(&Bs[kk][tx << 2]);
            float ar[4] = {a4.x, a4.y, a4.z, a4.w};
            float br4[4] = {b4.x, b4.y, b4.z, b4.w};
#pragma unroll
            for (int i = 0; i < 4; i++)
#pragma unroll
                for (int j = 0; j < 4; j++)
                    acc[i][j] = fmaf(ar[i], br4[j], acc[i][j]);
        }
        __syncthreads();
    }
#pragma unroll
    for (int i = 0; i < 4; i++) {
        int row = m0 + (ty << 2) + i;
#pragma unroll
        for (int j = 0; j < 4; j++) {
            int col = n0 + (tx << 2) + j;
            if (col < N) {
                float v = acc[i][j] * scale;
                if (bias) v += bias[col];
                C[row * ldc + col] = v;
            }
        }
    }
}

// ---------------- softmax over rows of 1024 ----------------
__global__ void __launch_bounds__(256) softmax_kernel(float* __restrict__ S) {
    float* p = S + blockIdx.x * MK;
    __shared__ float red[256];
    int tid = threadIdx.x;
    float m = -3.4e38f;
    for (int c = tid; c < MK; c += 256) m = fmaxf(m, p[c]);
    red[tid] = m; __syncthreads();
    for (int off = 128; off; off >>= 1) { if (tid < off) red[tid] = fmaxf(red[tid], red[tid + off]); __syncthreads(); }
    float mx = red[0];
    __syncthreads();
    float s = 0.f;
    for (int c = tid; c < MK; c += 256) { float e = expf(p[c] - mx); p[c] = e; s += e; }
    red[tid] = s; __syncthreads();
    for (int off = 128; off; off >>= 1) { if (tid < off) red[tid] += red[tid + off]; __syncthreads(); }
    float sum = red[0];
    __syncthreads();
    for (int c = tid; c < MK; c += 256) p[c] = p[c] / sum;
}

// ---------------- unmerge scatter into final output ----------------
__global__ void __launch_bounds__(256) unmerge_kernel(const float* __restrict__ proj, float* __restrict__ out,
    const int* __restrict__ a_idx, const int* __restrict__ b_idx,
    const int* __restrict__ perm, const int* __restrict__ dst)
{
    int rid = blockIdx.x;
    int srcrow, tok;
    if (rid < NDQ) { srcrow = UQ + rid; tok = b_idx[rid]; }
    else if (rid < NDQ + UQ) { int u = rid - NDQ; srcrow = u; tok = a_idx[perm[RQ + u]]; }
    else { int e = rid - (NDQ + UQ); srcrow = UQ + dst[e]; tok = a_idx[perm[e]]; }
    const float* s = proj + srcrow * CC;
    float* d = out + tok * CC;
    for (int c = threadIdx.x; c < CC; c += 256) d[c] = s[c];
}

// ---------------- host launcher ----------------
extern "C" void kernel_launch(void* const* d_in, const int* in_sizes, int n_in,
                              void* d_out, int out_size)
{
    (void)in_sizes; (void)n_in; (void)out_size;
    const float* x   = (const float*)d_in[0];
    const float* srw = (const float*)d_in[1];
    const float* srb = (const float*)d_in[2];
    const float* lng = (const float*)d_in[3];
    const float* lnb = (const float*)d_in[4];
    const float* Wq  = (const float*)d_in[5];
    const float* Wkv = (const float*)d_in[6];
    const float* Wp  = (const float*)d_in[7];
    const float* bp  = (const float*)d_in[8];
    float* out = (float*)d_out;

    float *bt, *xk, *mnq, *mnk, *nvq, *nvk, *xq, *xkm, *qm, *kvm, *S, *ao, *proj;
    unsigned long long *keyq, *keyk;
    int *permq, *permk, *dstq, *dstk, *cntq, *cntk, *aq, *bq, *ak, *bk;
    cudaGetSymbolAddress((void**)&bt, g_bt);
    cudaGetSymbolAddress((void**)&xk, g_xk);
    cudaGetSymbolAddress((void**)&mnq, g_mnq);
    cudaGetSymbolAddress((void**)&mnk, g_mnk);
    cudaGetSymbolAddress((void**)&nvq, g_nvq);
    cudaGetSymbolAddress((void**)&nvk, g_nvk);
    cudaGetSymbolAddress((void**)&xq, g_xq);
    cudaGetSymbolAddress((void**)&xkm, g_xkm);
    cudaGetSymbolAddress((void**)&qm, g_qm);
    cudaGetSymbolAddress((void**)&kvm, g_kvm);
    cudaGetSymbolAddress((void**)&S, g_S);
    cudaGetSymbolAddress((void**)&ao, g_ao);
    cudaGetSymbolAddress((void**)&proj, g_proj);
    cudaGetSymbolAddress((void**)&keyq, g_keyq);
    cudaGetSymbolAddress((void**)&keyk, g_keyk);
    cudaGetSymbolAddress((void**)&permq, g_permq);
    cudaGetSymbolAddress((void**)&permk, g_permk);
    cudaGetSymbolAddress((void**)&dstq, g_dstq);
    cudaGetSymbolAddress((void**)&dstk, g_dstk);
    cudaGetSymbolAddress((void**)&cntq, g_cntq);
    cudaGetSymbolAddress((void**)&cntk, g_cntk);
    cudaGetSymbolAddress((void**)&aq, g_aq);
    cudaGetSymbolAddress((void**)&bq, g_bq);
    cudaGetSymbolAddress((void**)&ak, g_ak);
    cudaGetSymbolAddress((void**)&bk, g_bk);

    // index tables
    build_idx_kernel<<<(NQ + 255) / 256, 256>>>(D0, H0, W0, aq, bq);
    build_idx_kernel<<<(N2 + 255) / 256, 256>>>(D0 / 2, H0 / 2, W0 / 2, ak, bk);

    // conv3d + LN
    transpose_w_kernel<<<(8 * CC * CC + 255) / 256, 256>>>(srw, bt);
    conv_kernel<<<dim3(CC / 64, N2 / 64), 256>>>(x, bt, srb, xk);
    ln_kernel<<<N2, 256>>>(xk, lng, lnb);

    // q-side BSM
    rownorm_kernel<<<NQ, 256>>>(x, mnq);
    set_u64_kernel<<<(NAQ + 255) / 256, 256>>>(keyq, NAQ);
    score_max_kernel<<<dim3(NDQ / 64, NAQ / 64), 256>>>(mnq, aq, bq, keyq);
    unpack_val_kernel<<<(NAQ + 255) / 256, 256>>>(keyq, nvq, NAQ);
    rank_kernel<<<NAQ / 256, 256>>>(nvq, permq, NAQ);
    set_int_kernel<<<(NDQ + 255) / 256, 256>>>(cntq, NDQ, 1);
    fill_dst_kernel<<<(RQ + 255) / 256, 256>>>(permq, keyq, dstq, cntq, RQ);
    merge_gather_kernel<<<MQ, 256>>>(x, xq, aq, bq, permq, UQ, RQ);
    scatter_add_kernel<<<RQ, 256>>>(x, xq, aq, permq, dstq, UQ);
    div_cnt_kernel<<<NDQ, 256>>>(xq, cntq, UQ);

    // kv-side BSM
    rownorm_kernel<<<N2, 256>>>(xk, mnk);
    set_u64_kernel<<<(NAK + 255) / 256, 256>>>(keyk, NAK);
    score_max_kernel<<<dim3(NDK / 64, NAK / 64), 256>>>(mnk, ak, bk, keyk);
    unpack_val_kernel<<<(NAK + 255) / 256, 256>>>(keyk, nvk, NAK);
    rank_kernel<<<NAK / 256, 256>>>(nvk, permk, NAK);
    set_int_kernel<<<1, 256>>>(cntk, NDK, 1);
    fill_dst_kernel<<<(RK + 255) / 256, 256>>>(permk, keyk, dstk, cntk, RK);
    merge_gather_kernel<<<MK, 256>>>(xk, xkm, ak, bk, permk, UK, RK);
    scatter_add_kernel<<<RK, 256>>>(xk, xkm, ak, permk, dstk, UK);
    div_cnt_kernel<<<NDK, 256>>>(xkm, cntk, UK);

    // projections
    gemm64_kernel<true><<<dim3(CC / 64, MQ / 64), 256>>>(xq, CC, Wq, CC, qm, CC, nullptr, 1.f, MQ, CC, CC);
    gemm64_kernel<true><<<dim3(2 * CC / 64, MK / 64), 256>>>(xkm, CC, Wkv, CC, kvm, 2 * CC, nullptr, 1.f, MK, 2 * CC, CC);

    // attention per head
    float scale = 1.0f / sqrtf((float)HD);
    for (int h = 0; h < HEADS; h++) {
        gemm64_kernel<true><<<dim3(MK / 64, MQ / 64), 256>>>(
            qm + h * HD, CC, kvm + h * HD, 2 * CC, S, MK, nullptr, scale, MQ, MK, HD);
        softmax_kernel<<<MQ, 256>>>(S);
        gemm64_kernel<false><<<dim3((HD + 63) / 64, MQ / 64), 256>>>(
            S, MK, kvm + CC + h * HD, 2 * CC, ao + h * HD, CC, nullptr, 1.f, MQ, HD, MK);
    }

    // output projection + unmerge
    gemm64_kernel<true><<<dim3(CC / 64, MQ / 64), 256>>>(ao, CC, Wp, CC, proj, CC, bp, 1.f, MQ, CC, CC);
    unmerge_kernel<<<NQ, 256>>>(proj, out, aq, bq, permq, dstq);
}

// round 5
// speedup vs baseline: 1.5844x; 1.5844x over previous
#include <cuda_runtime.h>
#include <cuda_bf16.h>
#include <math.h>
#include <stdint.h>

// ---------------- static problem sizes ----------------
#define CC    768
#define D0    16
#define H0    32
#define W0    32
#define NQ    16384
#define NDQ   2048
#define NAQ   14336
#define RQ    8192
#define UQ    6144
#define MQ    8192
#define N2    2048
#define NDK   256
#define NAK   1792
#define RK    1024
#define UK    768
#define MK    1024
#define HEADS 8
#define HD    96

typedef __nv_bfloat16 bf16;
typedef unsigned long long u64;

// ---------------- device scratch ----------------
__device__ float g_xk[N2 * CC];
__device__ float g_mnq[NQ * CC];
__device__ float g_mnk[N2 * CC];
__device__ u64   g_keyq[NAQ];
__device__ u64   g_keyk[NAK];
__device__ float g_nvq[NAQ];
__device__ float g_nvk[NAK];
__device__ float g_rmax[NAQ];
__device__ int g_permq[NAQ];
__device__ int g_permk[NAK];
__device__ int g_dstq[RQ];
__device__ int g_dstk[RK];
__device__ int g_cntq[NDQ];
__device__ int g_cntk[NDK];
__device__ int g_aq[NAQ];
__device__ int g_bq[NDQ];
__device__ int g_ak[NAK];
__device__ int g_bk[NDK];
__device__ int g_ctok[8 * N2];
__device__ float g_xq[MQ * CC];
__device__ float g_xkm[MK * CC];
__device__ float g_qm[MQ * CC];
__device__ float g_kvm[MK * 2 * CC];
__device__ float g_S[(long)HEADS * MQ * MK];   // also holds BSM score matrices earlier
__device__ float g_ao[MQ * CC];
__device__ float g_proj[MQ * CC];

// bf16 planes
__device__ bf16 g_x3[3][NQ * CC];
__device__ bf16 g_bt3[3][8 * CC * CC];
__device__ bf16 g_mq1[NQ * CC];
__device__ bf16 g_mk1[N2 * CC];
__device__ bf16 g_xq2[2][MQ * CC];
__device__ bf16 g_xkm2[2][MK * CC];
__device__ bf16 g_wq2[2][CC * CC];
__device__ bf16 g_wkv2[2][2 * CC * CC];
__device__ bf16 g_wp2[2][CC * CC];
__device__ bf16 g_qm2[2][MQ * CC];
__device__ bf16 g_kvm2[2][MK * 2 * CC];
__device__ bf16 g_vp2[2][HEADS * HD * MK];
__device__ bf16 g_ao2[2][MQ * CC];

__device__ __forceinline__ uint32_t pkbf(bf16 a, bf16 b) {
    return (uint32_t)__bfloat16_as_ushort(a) | ((uint32_t)__bfloat16_as_ushort(b) << 16);
}

#define MMA16816(d, a, b0v, b1v) \
    asm volatile("mma.sync.aligned.m16n8k16.row.col.f32.bf16.bf16.f32 " \
        "{%0,%1,%2,%3}, {%4,%5,%6,%7}, {%8,%9}, {%0,%1,%2,%3};" \
        : "+f"((d)[0]), "+f"((d)[1]), "+f"((d)[2]), "+f"((d)[3]) \
        : "r"((a)[0]), "r"((a)[1]), "r"((a)[2]), "r"((a)[3]), "r"(b0v), "r"(b1v))

// ---------------- mma.sync split-bf16 GEMM engine ----------------
// C[M,N] (+= over taps/products) = scale * A[M,K] @ B[N,K]^T (+bias)
// NPR=1: plain bf16. NPR=3: 2-way split (hi*hi,hi*lo,lo*hi). NPR=6: 3-way split.
// AS32: A fp32, split hi/lo on the fly. Block tile 128x128, k-tile 32, 8 warps (2x4),
// warp tile 64x32, smem stride 40 bf16 (80B) -> conflict-free fragment loads.
template <int NPR, bool AS32>
__global__ void __launch_bounds__(256) mmg(
    const void* A0v, const void* A1v, const void* A2v, long lda, long ahs,
    const bf16* B0, const bf16* B1, const bf16* B2, long ldb, long bhs, long bseg,
    float* C, long ldc, long chs, const float* bias, float scale,
    int N, int K, int ntap, const int* gA, int gAs, const int* gB)
{
    constexpr int nA = (NPR == 6) ? 3 : (NPR == 3) ? 2 : 1;
    constexpr int nB = nA;
    constexpr int TBb = 10240;  // bytes per tile plane: 128 rows * 80 B
    extern __shared__ char sm[];
    char* SA = sm;
    char* SB = sm + nA * TBb;

    const int tid = threadIdx.x, lane = tid & 31, wid = tid >> 5;
    const int wm = wid >> 2, wn = wid & 3;            // warps 2(m) x 4(n)
    const int m0 = blockIdx.y * 128, n0 = blockIdx.x * 128, z = blockIdx.z;
    const int lrow = tid >> 1, hf = tid & 1;          // loader: row, 16-col half
    const int lq = lane >> 2, lr = lane & 3;          // quad decomposition

    float acc[4][4][4];
#pragma unroll
    for (int i = 0; i < 4; i++)
#pragma unroll
        for (int j = 0; j < 4; j++)
#pragma unroll
            for (int t = 0; t < 4; t++) acc[i][j][t] = 0.f;

    for (int tap = 0; tap < ntap; tap++) {
        const long arow = gA ? (long)gA[tap * gAs + m0 + lrow] : (long)(m0 + lrow);
        const int nrow = n0 + lrow;
        const bool bval = nrow < N;
        const long brow = bval ? (gB ? (long)gB[nrow] : (long)nrow) : 0;

        for (int k0 = 0; k0 < K; k0 += 32) {
            // ---- stage A ----
            if constexpr (AS32) {
                const float* src = (const float*)A0v + (long)z * ahs + arow * lda + k0 + hf * 16;
                char* d0 = SA + lrow * 80 + hf * 32;
                char* d1 = d0 + TBb;
#pragma unroll
                for (int s = 0; s < 2; s++) {
                    float4 va = *(const float4*)(src + s * 8);
                    float4 vb = *(const float4*)(src + s * 8 + 4);
                    bf16 h0 = __float2bfloat16(va.x), h1 = __float2bfloat16(va.y);
                    bf16 h2 = __float2bfloat16(va.z), h3 = __float2bfloat16(va.w);
                    bf16 h4 = __float2bfloat16(vb.x), h5 = __float2bfloat16(vb.y);
                    bf16 h6 = __float2bfloat16(vb.z), h7 = __float2bfloat16(vb.w);
                    uint4 hv = make_uint4(pkbf(h0, h1), pkbf(h2, h3), pkbf(h4, h5), pkbf(h6, h7));
                    bf16 l0 = __float2bfloat16(va.x - __bfloat162float(h0));
                    bf16 l1 = __float2bfloat16(va.y - __bfloat162float(h1));
                    bf16 l2 = __float2bfloat16(va.z - __bfloat162float(h2));
                    bf16 l3 = __float2bfloat16(va.w - __bfloat162float(h3));
                    bf16 l4 = __float2bfloat16(vb.x - __bfloat162float(h4));
                    bf16 l5 = __float2bfloat16(vb.y - __bfloat162float(h5));
                    bf16 l6 = __float2bfloat16(vb.z - __bfloat162float(h6));
                    bf16 l7 = __float2bfloat16(vb.w - __bfloat162float(h7));
                    uint4 lv = make_uint4(pkbf(l0, l1), pkbf(l2, l3), pkbf(l4, l5), pkbf(l6, l7));
                    *(uint4*)(d0 + s * 16) = hv;
                    *(uint4*)(d1 + s * 16) = lv;
                }
            } else {
                const bf16* Ab[3] = {(const bf16*)A0v, (const bf16*)A1v, (const bf16*)A2v};
#pragma unroll
                for (int p = 0; p < nA; p++) {
                    const bf16* src = Ab[p] + (long)z * ahs + arow * lda + k0 + hf * 16;
                    char* dst = SA + p * TBb + lrow * 80 + hf * 32;
                    *(uint4*)(dst) = *(const uint4*)(src);
                    *(uint4*)(dst + 16) = *(const uint4*)(src + 8);
                }
            }
            // ---- stage B ----
            {
                const bf16* Bb[3] = {B0, B1, B2};
#pragma unroll
                for (int p = 0; p < nB; p++) {
                    uint4 v0 = make_uint4(0, 0, 0, 0), v1 = v0;
                    if (bval) {
                        const bf16* src = Bb[p] + (long)z * bhs + (long)tap * bseg + brow * ldb + k0 + hf * 16;
                        v0 = *(const uint4*)(src);
                        v1 = *(const uint4*)(src + 8);
                    }
                    char* dst = SB + p * TBb + lrow * 80 + hf * 32;
                    *(uint4*)(dst) = v0;
                    *(uint4*)(dst + 16) = v1;
                }
            }
            __syncthreads();
            // ---- compute ----
            const int pa6[6] = {0, 0, 1, 1, 0, 2}, pb6[6] = {0, 1, 0, 1, 2, 0};
#pragma unroll
            for (int pr = 0; pr < NPR; pr++) {
                const int pA = (NPR == 1) ? 0 : pa6[pr];
                const int pB = (NPR == 1) ? 0 : pb6[pr];
                const char* Ab = SA + pA * TBb;
                const char* Bb = SB + pB * TBb;
#pragma unroll
                for (int ks = 0; ks < 2; ks++) {
                    const int kb = ks * 16;
                    uint32_t af[4][4];
#pragma unroll
                    for (int i = 0; i < 4; i++) {
                        const int r = wm * 64 + i * 16 + lq;
                        const int c = kb + lr * 2;
                        af[i][0] = *(const uint32_t*)(Ab + r * 80 + c * 2);
                        af[i][1] = *(const uint32_t*)(Ab + (r + 8) * 80 + c * 2);
                        af[i][2] = *(const uint32_t*)(Ab + r * 80 + (c + 8) * 2);
                        af[i][3] = *(const uint32_t*)(Ab + (r + 8) * 80 + (c + 8) * 2);
                    }
#pragma unroll
                    for (int j = 0; j < 4; j++) {
                        const int nn = wn * 32 + j * 8 + lq;
                        const int kk = kb + lr * 2;
                        uint32_t b0 = *(const uint32_t*)(Bb + nn * 80 + kk * 2);
                        uint32_t b1 = *(const uint32_t*)(Bb + nn * 80 + (kk + 8) * 2);
#pragma unroll
                        for (int i = 0; i < 4; i++) MMA16816(acc[i][j], af[i], b0, b1);
                    }
                }
            }
            __syncthreads();
        }
    }
    // ---- epilogue ----
#pragma unroll
    for (int i = 0; i < 4; i++) {
        const int r = m0 + wm * 64 + i * 16 + lq;
#pragma unroll
        for (int j = 0; j < 4; j++) {
            const int cb = n0 + wn * 32 + j * 8 + lr * 2;
            if (cb < N) {
                float b0 = bias ? bias[cb] : 0.f;
                float b1 = bias ? bias[cb + 1] : 0.f;
                float* p0 = C + (long)z * chs + (long)r * ldc + cb;
                float* p1 = C + (long)z * chs + (long)(r + 8) * ldc + cb;
                p0[0] = acc[i][j][0] * scale + b0;
                p0[1] = acc[i][j][1] * scale + b1;
                p1[0] = acc[i][j][2] * scale + b0;
                p1[1] = acc[i][j][3] * scale + b1;
            }
        }
    }
}

// ---------------- utility / prep kernels ----------------
__global__ void set_int_kernel(int* p, int n, int v) {
    int i = blockIdx.x * 256 + threadIdx.x;
    if (i < n) p[i] = v;
}
__global__ void build_idx_kernel(int D, int H, int W, int* a_idx, int* b_idx) {
    int n = D * H * W;
    int t = blockIdx.x * 256 + threadIdx.x;
    if (t >= n) return;
    int z = t / (H * W), y = (t / W) % H, xx = t % W;
    int hw2 = (H >> 1) * (W >> 1);
    if (((z | y | xx) & 1) == 0) {
        b_idx[(z >> 1) * hw2 + (y >> 1) * (W >> 1) + (xx >> 1)] = t;
    } else {
        int cez = (z + 1) >> 1, cey = (y + 1) >> 1, cex = (xx + 1) >> 1;
        int before = cez * hw2;
        if ((z & 1) == 0) { before += cey * (W >> 1); if ((y & 1) == 0) before += cex; }
        a_idx[t - before] = t;
    }
}
__global__ void conv_tok_kernel(int* t) {
    int i = blockIdx.x * 256 + threadIdx.x;
    if (i >= 8 * N2) return;
    int tap = i >> 11, m = i & 2047;
    int kz = tap >> 2, ky = (tap >> 1) & 1, kx = tap & 1;
    int z2 = m >> 8, y2 = (m >> 4) & 15, x2 = m & 15;
    t[i] = (2 * z2 + kz) * (H0 * W0) + (2 * y2 + ky) * W0 + (2 * x2 + kx);
}
__global__ void split3_kernel(const float* __restrict__ s, bf16* p0, bf16* p1, bf16* p2, long n) {
    long i = (long)blockIdx.x * 256 + threadIdx.x;
    if (i >= n) return;
    float v = s[i];
    bf16 h = __float2bfloat16(v); float r = v - __bfloat162float(h);
    bf16 m = __float2bfloat16(r); float r2 = r - __bfloat162float(m);
    p0[i] = h; p1[i] = m; p2[i] = __float2bfloat16(r2);
}
__global__ void split2_kernel(const float* __restrict__ s, bf16* p0, bf16* p1, long n) {
    long i = (long)blockIdx.x * 256 + threadIdx.x;
    if (i >= n) return;
    float v = s[i];
    bf16 h = __float2bfloat16(v);
    p0[i] = h; p1[i] = __float2bfloat16(v - __bfloat162float(h));
}
__global__ void cvt1_kernel(const float* __restrict__ s, bf16* p0, long n) {
    long i = (long)blockIdx.x * 256 + threadIdx.x;
    if (i < n) p0[i] = __float2bfloat16(s[i]);
}
__global__ void split3_bt_kernel(const float* __restrict__ w, bf16* p0, bf16* p1, bf16* p2) {
    long i = (long)blockIdx.x * 256 + threadIdx.x;
    if (i >= (long)8 * CC * CC) return;
    int tap = (int)(i / (CC * CC));
    int rem = (int)(i - (long)tap * CC * CC);
    int n = rem / CC, k = rem - n * CC;
    float v = w[(long)n * (CC * 8) + k * 8 + tap];
    bf16 h = __float2bfloat16(v); float r = v - __bfloat162float(h);
    bf16 m = __float2bfloat16(r);
    p0[i] = h; p1[i] = m; p2[i] = __float2bfloat16(r - __bfloat162float(m));
}
// kvm v-part transposed -> [8][96][1024], 2 planes
__global__ void split_vT_kernel(const float* __restrict__ kvm, bf16* p0, bf16* p1) {
    long i = (long)blockIdx.x * 256 + threadIdx.x;
    if (i >= (long)HEADS * HD * MK) return;
    int h = (int)(i / (HD * MK));
    int rem = (int)(i - (long)h * HD * MK);
    int n = rem >> 10, k = rem & (MK - 1);
    float v = kvm[(long)k * (2 * CC) + CC + h * HD + n];
    bf16 hi = __float2bfloat16(v);
    p0[i] = hi; p1[i] = __float2bfloat16(v - __bfloat162float(hi));
}

// ---------------- LayerNorm / rownorm ----------------
__global__ void __launch_bounds__(256) ln_kernel(float* __restrict__ xk,
    const float* __restrict__ g, const float* __restrict__ b)
{
    int row = blockIdx.x;
    float* p = xk + (long)row * CC;
    __shared__ float red[256];
    int tid = threadIdx.x;
    float s = 0.f;
    for (int c = tid; c < CC; c += 256) s += p[c];
    red[tid] = s; __syncthreads();
    for (int off = 128; off; off >>= 1) { if (tid < off) red[tid] += red[tid + off]; __syncthreads(); }
    float mean = red[0] / (float)CC;
    __syncthreads();
    float v = 0.f;
    for (int c = tid; c < CC; c += 256) { float d = p[c] - mean; v += d * d; }
    red[tid] = v; __syncthreads();
    for (int off = 128; off; off >>= 1) { if (tid < off) red[tid] += red[tid + off]; __syncthreads(); }
    float var = red[0] / (float)CC;
    float inv = (float)(1.0 / sqrt((double)var + 1e-5));
    __syncthreads();
    for (int c = tid; c < CC; c += 256) p[c] = (p[c] - mean) * inv * g[c] + b[c];
}
__global__ void __launch_bounds__(256) rownorm_kernel(const float* __restrict__ src, float* __restrict__ dst) {
    int row = blockIdx.x;
    const float* p = src + (long)row * CC;
    float* q = dst + (long)row * CC;
    __shared__ float red[256];
    int tid = threadIdx.x;
    float s = 0.f;
    for (int c = tid; c < CC; c += 256) { float v = p[c]; s += v * v; }
    red[tid] = s; __syncthreads();
    for (int off = 128; off; off >>= 1) { if (tid < off) red[tid] += red[tid + off]; __syncthreads(); }
    float inv = (float)(1.0 / sqrt((double)red[0]));
    for (int c = tid; c < CC; c += 256) q[c] = p[c] * inv;
}

// ---------------- two-phase BSM scoring ----------------
__global__ void __launch_bounds__(256) rowmax_kernel(const float* __restrict__ S, float* __restrict__ rmax, int ncol) {
    int row = blockIdx.x * 8 + (threadIdx.x >> 5);
    int lane = threadIdx.x & 31;
    const float* p = S + (long)row * ncol;
    float m = -3.4e38f;
    for (int c = lane; c < ncol; c += 32) m = fmaxf(m, p[c]);
    for (int off = 16; off; off >>= 1) m = fmaxf(m, __shfl_xor_sync(0xffffffffu, m, off));
    if (lane == 0) rmax[row] = m;
}
// warp per src: exact fp32 re-evaluation of candidates within margin of cheap max
__global__ void __launch_bounds__(256) refine_kernel(
    const float* __restrict__ S, int ncol, const float* __restrict__ mn,
    const int* __restrict__ a_idx, const int* __restrict__ b_idx,
    const float* __restrict__ rmax, u64* __restrict__ key, float margin)
{
    int row = blockIdx.x * 8 + (threadIdx.x >> 5);
    int lane = threadIdx.x & 31;
    const float* p = S + (long)row * ncol;
    float thr = rmax[row] - margin;
    const float* av = mn + (long)a_idx[row] * CC;
    float bestv = -3.4e38f;
    int bestd = 0;
    for (int base = 0; base < ncol; base += 32) {
        float s = p[base + lane];
        unsigned m = __ballot_sync(0xffffffffu, s >= thr);
        while (m) {
            int b = __ffs(m) - 1;
            m &= m - 1;
            int dst = base + b;
            const float* bv = mn + (long)b_idx[dst] * CC;
            float part = 0.f;
            for (int c = lane; c < CC; c += 32) part += av[c] * bv[c];
            for (int off = 16; off; off >>= 1) part += __shfl_xor_sync(0xffffffffu, part, off);
            if (part > bestv) { bestv = part; bestd = dst; }
        }
    }
    if (lane == 0) {
        unsigned u = __float_as_uint(bestv);
        unsigned o = (u & 0x80000000u) ? ~u : (u | 0x80000000u);
        key[row] = ((u64)o << 32) | (unsigned)(~bestd);
    }
}

// ---------------- BSM index machinery ----------------
__global__ void unpack_val_kernel(const u64* __restrict__ key, float* __restrict__ val, int n) {
    int i = blockIdx.x * 256 + threadIdx.x;
    if (i >= n) return;
    uint32_t o = (uint32_t)(key[i] >> 32);
    uint32_t u = (o & 0x80000000u) ? (o ^ 0x80000000u) : ~o;
    val[i] = __uint_as_float(u);
}
__global__ void __launch_bounds__(256) rank_kernel(const float* __restrict__ v, int* __restrict__ perm, int n) {
    int i = blockIdx.x * 256 + threadIdx.x;
    float vi = (i < n) ? v[i] : 0.f;
    int r = 0;
    __shared__ float sv[256];
    for (int base = 0; base < n; base += 256) {
        int j = base + threadIdx.x;
        sv[threadIdx.x] = (j < n) ? v[j] : -3.4e38f;
        __syncthreads();
        int lim = min(256, n - base);
        for (int t = 0; t < lim; t++) {
            float vj = sv[t];
            int j2 = base + t;
            if (vj > vi || (vj == vi && j2 < i)) r++;
        }
        __syncthreads();
    }
    if (i < n) perm[r] = i;
}
__global__ void fill_dst_kernel(const int* __restrict__ perm, const u64* __restrict__ key,
                                int* __restrict__ dst, int* __restrict__ cnt, int R) {
    int e = blockIdx.x * 256 + threadIdx.x;
    if (e >= R) return;
    int s = perm[e];
    uint32_t low = (uint32_t)(key[s]);
    int dd = (int)(~low);
    dst[e] = dd;
    atomicAdd(&cnt[dd], 1);
}
__global__ void __launch_bounds__(256) merge_gather_kernel(const float* __restrict__ src, float* __restrict__ buf,
    const int* __restrict__ a_idx, const int* __restrict__ b_idx,
    const int* __restrict__ perm, int U, int R)
{
    int row = blockIdx.x;
    int tok = (row < U) ? a_idx[perm[R + row]] : b_idx[row - U];
    const float* s = src + (long)tok * CC;
    float* d = buf + (long)row * CC;
    for (int c = threadIdx.x; c < CC; c += 256) d[c] = s[c];
}
__global__ void __launch_bounds__(256) scatter_add_kernel(const float* __restrict__ src, float* __restrict__ buf,
    const int* __restrict__ a_idx, const int* __restrict__ perm, const int* __restrict__ dst, int U)
{
    int e = blockIdx.x;
    int tok = a_idx[perm[e]];
    float* d = buf + (long)(U + dst[e]) * CC;
    const float* s = src + (long)tok * CC;
    for (int c = threadIdx.x; c < CC; c += 256) atomicAdd(&d[c], s[c]);
}
__global__ void __launch_bounds__(256) div_cnt_kernel(float* __restrict__ buf, const int* __restrict__ cnt, int U) {
    int dr = blockIdx.x;
    float cf = (float)cnt[dr];
    float* p = buf + (long)(U + dr) * CC;
    for (int c = threadIdx.x; c < CC; c += 256) p[c] = p[c] / cf;
}

// ---------------- softmax ----------------
__global__ void __launch_bounds__(256) softmax_kernel(float* __restrict__ S) {
    float* p = S + (long)blockIdx.x * MK;
    __shared__ float red[256];
    int tid = threadIdx.x;
    float m = -3.4e38f;
    for (int c = tid; c < MK; c += 256) m = fmaxf(m, p[c]);
    red[tid] = m; __syncthreads();
    for (int off = 128; off; off >>= 1) { if (tid < off) red[tid] = fmaxf(red[tid], red[tid + off]); __syncthreads(); }
    float mx = red[0];
    __syncthreads();
    float s = 0.f;
    for (int c = tid; c < MK; c += 256) { float e = expf(p[c] - mx); p[c] = e; s += e; }
    red[tid] = s; __syncthreads();
    for (int off = 128; off; off >>= 1) { if (tid < off) red[tid] += red[tid + off]; __syncthreads(); }
    float sum = red[0];
    __syncthreads();
    for (int c = tid; c < MK; c += 256) p[c] = p[c] / sum;
}

// ---------------- unmerge ----------------
__global__ void __launch_bounds__(256) unmerge_kernel(const float* __restrict__ proj, float* __restrict__ out,
    const int* __restrict__ a_idx, const int* __restrict__ b_idx,
    const int* __restrict__ perm, const int* __restrict__ dst)
{
    int rid = blockIdx.x;
    int srcrow, tok;
    if (rid < NDQ) { srcrow = UQ + rid; tok = b_idx[rid]; }
    else if (rid < NDQ + UQ) { int u = rid - NDQ; srcrow = u; tok = a_idx[perm[RQ + u]]; }
    else { int e = rid - (NDQ + UQ); srcrow = UQ + dst[e]; tok = a_idx[perm[e]]; }
    const float* s = proj + (long)srcrow * CC;
    float* d = out + (long)tok * CC;
    for (int c = threadIdx.x; c < CC; c += 256) d[c] = s[c];
}

// ---------------- host launcher ----------------
#define SM_NPR1 (2 * 10240)
#define SM_NPR3 (4 * 10240)
#define SM_NPR6 (6 * 10240)

extern "C" void kernel_launch(void* const* d_in, const int* in_sizes, int n_in,
                              void* d_out, int out_size)
{
    (void)in_sizes; (void)n_in; (void)out_size;
    const float* x   = (const float*)d_in[0];
    const float* srw = (const float*)d_in[1];
    const float* srb = (const float*)d_in[2];
    const float* lng = (const float*)d_in[3];
    const float* lnb = (const float*)d_in[4];
    const float* Wq  = (const float*)d_in[5];
    const float* Wkv = (const float*)d_in[6];
    const float* Wp  = (const float*)d_in[7];
    const float* bp  = (const float*)d_in[8];
    float* out = (float*)d_out;

    cudaFuncSetAttribute(mmg<6, false>, cudaFuncAttributeMaxDynamicSharedMemorySize, SM_NPR6);
    cudaFuncSetAttribute(mmg<3, false>, cudaFuncAttributeMaxDynamicSharedMemorySize, SM_NPR3);
    cudaFuncSetAttribute(mmg<3, true>,  cudaFuncAttributeMaxDynamicSharedMemorySize, SM_NPR3);
    cudaFuncSetAttribute(mmg<1, false>, cudaFuncAttributeMaxDynamicSharedMemorySize, SM_NPR1);

    float *xk, *mnq, *mnk, *nvq, *nvk, *rmax, *xq, *xkm, *qm, *kvm, *S, *ao, *proj;
    u64 *keyq, *keyk;
    int *permq, *permk, *dstq, *dstk, *cntq, *cntk, *aq, *bq, *ak, *bk, *ctok;
    bf16 *x3, *bt3, *mq1, *mk1, *xq2, *xkm2, *wq2, *wkv2, *wp2, *qm2, *kvm2, *vp2, *ao2;
    cudaGetSymbolAddress((void**)&xk, g_xk);
    cudaGetSymbolAddress((void**)&mnq, g_mnq);
    cudaGetSymbolAddress((void**)&mnk, g_mnk);
    cudaGetSymbolAddress((void**)&nvq, g_nvq);
    cudaGetSymbolAddress((void**)&nvk, g_nvk);
    cudaGetSymbolAddress((void**)&rmax, g_rmax);
    cudaGetSymbolAddress((void**)&xq, g_xq);
    cudaGetSymbolAddress((void**)&xkm, g_xkm);
    cudaGetSymbolAddress((void**)&qm, g_qm);
    cudaGetSymbolAddress((void**)&kvm, g_kvm);
    cudaGetSymbolAddress((void**)&S, g_S);
    cudaGetSymbolAddress((void**)&ao, g_ao);
    cudaGetSymbolAddress((void**)&proj, g_proj);
    cudaGetSymbolAddress((void**)&keyq, g_keyq);
    cudaGetSymbolAddress((void**)&keyk, g_keyk);
    cudaGetSymbolAddress((void**)&permq, g_permq);
    cudaGetSymbolAddress((void**)&permk, g_permk);
    cudaGetSymbolAddress((void**)&dstq, g_dstq);
    cudaGetSymbolAddress((void**)&dstk, g_dstk);
    cudaGetSymbolAddress((void**)&cntq, g_cntq);
    cudaGetSymbolAddress((void**)&cntk, g_cntk);
    cudaGetSymbolAddress((void**)&aq, g_aq);
    cudaGetSymbolAddress((void**)&bq, g_bq);
    cudaGetSymbolAddress((void**)&ak, g_ak);
    cudaGetSymbolAddress((void**)&bk, g_bk);
    cudaGetSymbolAddress((void**)&ctok, g_ctok);
    cudaGetSymbolAddress((void**)&x3, g_x3);
    cudaGetSymbolAddress((void**)&bt3, g_bt3);
    cudaGetSymbolAddress((void**)&mq1, g_mq1);
    cudaGetSymbolAddress((void**)&mk1, g_mk1);
    cudaGetSymbolAddress((void**)&xq2, g_xq2);
    cudaGetSymbolAddress((void**)&xkm2, g_xkm2);
    cudaGetSymbolAddress((void**)&wq2, g_wq2);
    cudaGetSymbolAddress((void**)&wkv2, g_wkv2);
    cudaGetSymbolAddress((void**)&wp2, g_wp2);
    cudaGetSymbolAddress((void**)&qm2, g_qm2);
    cudaGetSymbolAddress((void**)&kvm2, g_kvm2);
    cudaGetSymbolAddress((void**)&vp2, g_vp2);
    cudaGetSymbolAddress((void**)&ao2, g_ao2);

    const long PXQ = (long)NQ * CC;
    const long PBT = (long)8 * CC * CC;
    const long PQ2 = (long)MQ * CC;
    const long PK2 = (long)MK * CC;
    const long PWQ = (long)CC * CC;
    const long PWKV = (long)2 * CC * CC;
    const long PQM = (long)MQ * CC;
    const long PKVM = (long)MK * 2 * CC;
    const long PVP = (long)HEADS * HD * MK;
    float* Skv = S + (long)NAQ * NDQ;

    // ---- index tables ----
    build_idx_kernel<<<(NQ + 255) / 256, 256>>>(D0, H0, W0, aq, bq);
    build_idx_kernel<<<(N2 + 255) / 256, 256>>>(D0 / 2, H0 / 2, W0 / 2, ak, bk);
    conv_tok_kernel<<<(8 * N2 + 255) / 256, 256>>>(ctok);

    // ---- splits ----
    split3_kernel<<<(int)((PXQ + 255) / 256), 256>>>(x, x3, x3 + PXQ, x3 + 2 * PXQ, PXQ);
    split3_bt_kernel<<<(int)((PBT + 255) / 256), 256>>>(srw, bt3, bt3 + PBT, bt3 + 2 * PBT);
    split2_kernel<<<(int)((PWQ + 255) / 256), 256>>>(Wq, wq2, wq2 + PWQ, PWQ);
    split2_kernel<<<(int)((PWKV + 255) / 256), 256>>>(Wkv, wkv2, wkv2 + PWKV, PWKV);
    split2_kernel<<<(int)((PWQ + 255) / 256), 256>>>(Wp, wp2, wp2 + PWQ, PWQ);

    // ---- conv3d (6-product) + LN ----
    mmg<6, false><<<dim3(CC / 128, N2 / 128, 1), 256, SM_NPR6>>>(
        x3, x3 + PXQ, x3 + 2 * PXQ, CC, 0,
        bt3, bt3 + PBT, bt3 + 2 * PBT, CC, 0, (long)CC * CC,
        xk, CC, 0, srb, 1.f, CC, CC, 8, ctok, N2, nullptr);
    ln_kernel<<<N2, 256>>>(xk, lng, lnb);

    // ---- q-side BSM (two-phase) ----
    rownorm_kernel<<<NQ, 256>>>(x, mnq);
    cvt1_kernel<<<(int)((PXQ + 255) / 256), 256>>>(mnq, mq1, PXQ);
    mmg<1, false><<<dim3(NDQ / 128, NAQ / 128, 1), 256, SM_NPR1>>>(
        mq1, nullptr, nullptr, CC, 0,
        mq1, nullptr, nullptr, CC, 0, 0,
        S, NDQ, 0, nullptr, 1.f, NDQ, CC, 1, aq, 0, bq);
    rowmax_kernel<<<NAQ / 8, 256>>>(S, rmax, NDQ);
    refine_kernel<<<NAQ / 8, 256>>>(S, NDQ, mnq, aq, bq, rmax, keyq, 2e-3f);
    unpack_val_kernel<<<(NAQ + 255) / 256, 256>>>(keyq, nvq, NAQ);
    rank_kernel<<<NAQ / 256, 256>>>(nvq, permq, NAQ);
    set_int_kernel<<<(NDQ + 255) / 256, 256>>>(cntq, NDQ, 1);
    fill_dst_kernel<<<(RQ + 255) / 256, 256>>>(permq, keyq, dstq, cntq, RQ);
    merge_gather_kernel<<<MQ, 256>>>(x, xq, aq, bq, permq, UQ, RQ);
    scatter_add_kernel<<<RQ, 256>>>(x, xq, aq, permq, dstq, UQ);
    div_cnt_kernel<<<NDQ, 256>>>(xq, cntq, UQ);

    // ---- kv-side BSM (two-phase) ----
    rownorm_kernel<<<N2, 256>>>(xk, mnk);
    cvt1_kernel<<<(int)(((long)N2 * CC + 255) / 256), 256>>>(mnk, mk1, (long)N2 * CC);
    mmg<1, false><<<dim3(NDK / 128, NAK / 128, 1), 256, SM_NPR1>>>(
        mk1, nullptr, nullptr, CC, 0,
        mk1, nullptr, nullptr, CC, 0, 0,
        Skv, NDK, 0, nullptr, 1.f, NDK, CC, 1, ak, 0, bk);
    rowmax_kernel<<<NAK / 8, 256>>>(Skv, rmax, NDK);
    refine_kernel<<<NAK / 8, 256>>>(Skv, NDK, mnk, ak, bk, rmax, keyk, 2e-3f);
    unpack_val_kernel<<<(NAK + 255) / 256, 256>>>(keyk, nvk, NAK);
    rank_kernel<<<NAK / 256, 256>>>(nvk, permk, NAK);
    set_int_kernel<<<1, 256>>>(cntk, NDK, 1);
    fill_dst_kernel<<<(RK + 255) / 256, 256>>>(permk, keyk, dstk, cntk, RK);
    merge_gather_kernel<<<MK, 256>>>(xk, xkm, ak, bk, permk, UK, RK);
    scatter_add_kernel<<<RK, 256>>>(xk, xkm, ak, permk, dstk, UK);
    div_cnt_kernel<<<NDK, 256>>>(xkm, cntk, UK);

    // ---- projections (3-product) ----
    split2_kernel<<<(int)((PQ2 + 255) / 256), 256>>>(xq, xq2, xq2 + PQ2, PQ2);
    split2_kernel<<<(int)((PK2 + 255) / 256), 256>>>(xkm, xkm2, xkm2 + PK2, PK2);
    mmg<3, false><<<dim3(CC / 128, MQ / 128, 1), 256, SM_NPR3>>>(
        xq2, xq2 + PQ2, nullptr, CC, 0,
        wq2, wq2 + PWQ, nullptr, CC, 0, 0,
        qm, CC, 0, nullptr, 1.f, CC, CC, 1, nullptr, 0, nullptr);
    mmg<3, false><<<dim3(2 * CC / 128, MK / 128, 1), 256, SM_NPR3>>>(
        xkm2, xkm2 + PK2, nullptr, CC, 0,
        wkv2, wkv2 + PWKV, nullptr, CC, 0, 0,
        kvm, 2 * CC, 0, nullptr, 1.f, 2 * CC, CC, 1, nullptr, 0, nullptr);

    // ---- head prep ----
    split2_kernel<<<(int)((PQM + 255) / 256), 256>>>(qm, qm2, qm2 + PQM, PQM);
    split2_kernel<<<(int)((PKVM + 255) / 256), 256>>>(kvm, kvm2, kvm2 + PKVM, PKVM);
    split_vT_kernel<<<(int)((PVP + 255) / 256), 256>>>(kvm, vp2, vp2 + PVP);

    // ---- attention ----
    float scl = 1.0f / sqrtf((float)HD);
    mmg<3, false><<<dim3(MK / 128, MQ / 128, HEADS), 256, SM_NPR3>>>(
        qm2, qm2 + PQM, nullptr, CC, HD,
        kvm2, kvm2 + PKVM, nullptr, 2 * CC, HD, 0,
        S, MK, (long)MQ * MK, nullptr, scl, MK, HD, 1, nullptr, 0, nullptr);
    softmax_kernel<<<HEADS * MQ, 256>>>(S);
    mmg<3, true><<<dim3(1, MQ / 128, HEADS), 256, SM_NPR3>>>(
        S, nullptr, nullptr, MK, (long)MQ * MK,
        vp2, vp2 + PVP, nullptr, MK, (long)HD * MK, 0,
        ao, CC, HD, nullptr, 1.f, HD, MK, 1, nullptr, 0, nullptr);

    // ---- output projection + unmerge ----
    split2_kernel<<<(int)((PQ2 + 255) / 256), 256>>>(ao, ao2, ao2 + PQ2, PQ2);
    mmg<3, false><<<dim3(CC / 128, MQ / 128, 1), 256, SM_NPR3>>>(
        ao2, ao2 + PQ2, nullptr, CC, 0,
        wp2, wp2 + PWQ, nullptr, CC, 0, 0,
        proj, CC, 0, bp, 1.f, CC, CC, 1, nullptr, 0, nullptr);
    unmerge_kernel<<<NQ, 256>>>(proj, out, aq, bq, permq, dstq);
}

// round 6
// speedup vs baseline: 1.8215x; 1.1496x over previous
#include <cuda_runtime.h>
#include <cuda_bf16.h>
#include <math.h>
#include <stdint.h>

// ---------------- static problem sizes ----------------
#define CC    768
#define D0    16
#define H0    32
#define W0    32
#define NQ    16384
#define NDQ   2048
#define NAQ   14336
#define RQ    8192
#define UQ    6144
#define MQ    8192
#define N2    2048
#define NDK   256
#define NAK   1792
#define RK    1024
#define UK    768
#define MK    1024
#define HEADS 8
#define HD    96

typedef __nv_bfloat16 bf16;
typedef unsigned long long u64;

// ---------------- device scratch ----------------
__device__ float g_xk[N2 * CC];
__device__ float g_mnq[NQ * CC];
__device__ float g_mnk[N2 * CC];
__device__ u64   g_keyq[NAQ];
__device__ u64   g_keyk[NAK];
__device__ float g_nvq[NAQ];
__device__ float g_nvk[NAK];
__device__ float g_rmax[NAQ];
__device__ int g_permq[NAQ];
__device__ int g_permk[NAK];
__device__ int g_dstq[RQ];
__device__ int g_dstk[RK];
__device__ int g_cntq[NDQ];
__device__ int g_cntk[NDK];
__device__ int g_aq[NAQ];
__device__ int g_bq[NDQ];
__device__ int g_ak[NAK];
__device__ int g_bk[NDK];
__device__ int g_ctok[8 * N2];
__device__ float g_xq[MQ * CC];
__device__ float g_xkm[MK * CC];
__device__ float g_qm[MQ * CC];
__device__ float g_kvm[MK * 2 * CC];
__device__ float g_S[(long)HEADS * MQ * MK];
__device__ float g_ao[MQ * CC];
__device__ float g_proj[MQ * CC];

// bf16 planes
__device__ bf16 g_x3[3][NQ * CC];
__device__ bf16 g_bt3[3][8 * CC * CC];
__device__ bf16 g_mq1[NQ * CC];
__device__ bf16 g_mk1[N2 * CC];
__device__ bf16 g_xq2[2][MQ * CC];
__device__ bf16 g_xkm2[2][MK * CC];
__device__ bf16 g_wq2[2][CC * CC];
__device__ bf16 g_wkv2[2][2 * CC * CC];
__device__ bf16 g_wp2[2][CC * CC];
__device__ bf16 g_qp2[2][HEADS * MQ * 128];
__device__ bf16 g_kp2[2][HEADS * MK * 128];
__device__ bf16 g_vp2[2][HEADS * HD * MK];
__device__ bf16 g_ao2[2][MQ * CC];
__device__ bf16 g_sh[(long)HEADS * MQ * MK];
__device__ bf16 g_sl[(long)HEADS * MQ * MK];

__device__ __forceinline__ uint32_t smem_u32(const void* p) {
    uint32_t a;
    asm("{ .reg .u64 t; cvta.to.shared.u64 t, %1; cvt.u32.u64 %0, t; }" : "=r"(a) : "l"(p));
    return a;
}
__device__ __forceinline__ uint32_t pkbf(bf16 a, bf16 b) {
    return (uint32_t)__bfloat16_as_ushort(a) | ((uint32_t)__bfloat16_as_ushort(b) << 16);
}
#define SWZ(o) ((o) ^ (((o) >> 3) & 0x70))
#define MMA16816(d, a, b0v, b1v) \
    asm volatile("mma.sync.aligned.m16n8k16.row.col.f32.bf16.bf16.f32 " \
        "{%0,%1,%2,%3}, {%4,%5,%6,%7}, {%8,%9}, {%0,%1,%2,%3};" \
        : "+f"((d)[0]), "+f"((d)[1]), "+f"((d)[2]), "+f"((d)[3]) \
        : "r"((a)[0]), "r"((a)[1]), "r"((a)[2]), "r"((a)[3]), "r"(b0v), "r"(b1v))
#define LDSM4(r, a) \
    asm volatile("ldmatrix.sync.aligned.m8n8.x4.shared.b16 {%0,%1,%2,%3}, [%4];" \
        : "=r"((r)[0]), "=r"((r)[1]), "=r"((r)[2]), "=r"((r)[3]) : "r"(a))
#define CPA(dst, src, sz) \
    asm volatile("cp.async.cg.shared.global [%0], [%1], 16, %2;" :: "r"(dst), "l"(src), "r"(sz) : "memory")
#define CPCOMMIT() asm volatile("cp.async.commit_group;" ::: "memory")
#define CPWAIT1()  asm volatile("cp.async.wait_group 1;" ::: "memory")
#define CPWAIT0()  asm volatile("cp.async.wait_group 0;" ::: "memory")

// ---------------- pipelined ldmatrix mma.sync split-bf16 GEMM ----------------
// C[M,N] = scale * A[M,K] @ B[N,K]^T (+bias), over ntap segments.
// Block 128x128, k-tile 64, 2-stage cp.async pipeline, 8 warps (2m x 4n), warp 64x32.
template <int NPR>
__global__ void __launch_bounds__(256) mmg(
    const bf16* A0, const bf16* A1, const bf16* A2, long lda, long ahs,
    const bf16* B0, const bf16* B1, const bf16* B2, long ldb, long bhs, long bseg,
    float* C, long ldc, long chs, const float* bias, float scale,
    int N, int K, int ntap, const int* gA, int gAs, const int* gB)
{
    constexpr int nA = (NPR == 6) ? 3 : (NPR == 3) ? 2 : 1;
    constexpr int nB = nA;
    constexpr int PL = 16384;              // bytes per plane tile (128 x 128B)
    constexpr int STG = (nA + nB) * PL;    // bytes per stage
    extern __shared__ char sm[];
    const uint32_t su = smem_u32(sm);

    const int tid = threadIdx.x, lane = tid & 31, wid = tid >> 5;
    const int wm = wid >> 2, wn = wid & 3;
    const int m0 = blockIdx.y * 128, n0 = blockIdx.x * 128, z = blockIdx.z;
    const int lq = lane >> 2, lr = lane & 3;

    const int lrow = tid >> 1, hf = tid & 1;
    const int nrow = n0 + lrow;
    const bool bval = nrow < N;
    const long brow = bval ? (gB ? (long)gB[nrow] : (long)nrow) : 0;
    const uint32_t bsz = bval ? 16u : 0u;

    const int kc = K >> 6;
    const int nchunks = ntap * kc;

    const bf16* Ap[3] = {A0, A1, A2};
    const bf16* Bp[3] = {B0, B1, B2};

    uint32_t dsto[4];
#pragma unroll
    for (int s = 0; s < 4; s++) {
        uint32_t off = (uint32_t)(lrow * 128 + hf * 64 + s * 16);
        dsto[s] = su + SWZ(off);
    }

    float acc[4][4][4];
#pragma unroll
    for (int i = 0; i < 4; i++)
#pragma unroll
        for (int j = 0; j < 4; j++)
#pragma unroll
            for (int t = 0; t < 4; t++) acc[i][j][t] = 0.f;

    auto issue = [&](int c, int stg) {
        const int tap = c / kc;
        const int k0 = (c - tap * kc) << 6;
        const long arow = gA ? (long)gA[tap * gAs + m0 + lrow] : (long)(m0 + lrow);
        const uint32_t sb = stg ? (uint32_t)STG : 0u;
#pragma unroll
        for (int p = 0; p < nA; p++) {
            const bf16* s0 = Ap[p] + (long)z * ahs + arow * lda + k0 + hf * 32;
#pragma unroll
            for (int s = 0; s < 4; s++) CPA(dsto[s] + sb + p * PL, s0 + s * 8, 16u);
        }
#pragma unroll
        for (int p = 0; p < nB; p++) {
            const bf16* s0 = Bp[p] + (long)z * bhs + (long)tap * bseg + brow * ldb + k0 + hf * 32;
#pragma unroll
            for (int s = 0; s < 4; s++) CPA(dsto[s] + sb + (nA + p) * PL, s0 + s * 8, bsz);
        }
        CPCOMMIT();
    };

    auto compute = [&](int stg) {
        const uint32_t sb = su + (stg ? (uint32_t)STG : 0u);
        const int ra = wm * 64 + (lane & 15);
        const int rb = wn * 32 + (lane >> 3) * 8 + (lane & 7);
        const int pa6[6] = {0, 0, 1, 1, 0, 2}, pb6[6] = {0, 1, 0, 1, 2, 0};
#pragma unroll
        for (int ks = 0; ks < 4; ks++) {
            uint32_t af[nA][4][4];
#pragma unroll
            for (int p = 0; p < nA; p++)
#pragma unroll
                for (int i = 0; i < 4; i++) {
                    uint32_t off = (uint32_t)((ra + i * 16) * 128 + ks * 32 + ((lane >> 4) << 4));
                    LDSM4(af[p][i], sb + p * PL + SWZ(off));
                }
            uint32_t b0[nB][4], b1[nB][4];
#pragma unroll
            for (int p = 0; p < nB; p++) {
                uint32_t off0 = (uint32_t)(rb * 128 + ks * 32);
                LDSM4(b0[p], sb + (nA + p) * PL + SWZ(off0));
                uint32_t off1 = off0 + 16;
                LDSM4(b1[p], sb + (nA + p) * PL + SWZ(off1));
            }
#pragma unroll
            for (int pr = 0; pr < NPR; pr++) {
                const int pA = (NPR == 1) ? 0 : pa6[pr];
                const int pB = (NPR == 1) ? 0 : pb6[pr];
#pragma unroll
                for (int i = 0; i < 4; i++)
#pragma unroll
                    for (int j = 0; j < 4; j++)
                        MMA16816(acc[i][j], af[pA][i], b0[pB][j], b1[pB][j]);
            }
        }
    };

    issue(0, 0);
    for (int c = 0; c < nchunks; c++) {
        const int stg = c & 1;
        if (c + 1 < nchunks) { issue(c + 1, stg ^ 1); CPWAIT1(); }
        else CPWAIT0();
        __syncthreads();
        compute(stg);
        __syncthreads();
    }

    // ---- epilogue ----
#pragma unroll
    for (int i = 0; i < 4; i++) {
        const int r = m0 + wm * 64 + i * 16 + lq;
#pragma unroll
        for (int j = 0; j < 4; j++) {
            const int cb = n0 + wn * 32 + j * 8 + lr * 2;
            if (cb < N) {
                float bb0 = bias ? bias[cb] : 0.f;
                float bb1 = bias ? bias[cb + 1] : 0.f;
                float* p0 = C + (long)z * chs + (long)r * ldc + cb;
                float* p1 = C + (long)z * chs + (long)(r + 8) * ldc + cb;
                p0[0] = acc[i][j][0] * scale + bb0;
                p0[1] = acc[i][j][1] * scale + bb1;
                p1[0] = acc[i][j][2] * scale + bb0;
                p1[1] = acc[i][j][3] * scale + bb1;
            }
        }
    }
}

// ---------------- utility / prep kernels ----------------
__global__ void set_int_kernel(int* p, int n, int v) {
    int i = blockIdx.x * 256 + threadIdx.x;
    if (i < n) p[i] = v;
}
__global__ void build_idx_kernel(int D, int H, int W, int* a_idx, int* b_idx) {
    int n = D * H * W;
    int t = blockIdx.x * 256 + threadIdx.x;
    if (t >= n) return;
    int z = t / (H * W), y = (t / W) % H, xx = t % W;
    int hw2 = (H >> 1) * (W >> 1);
    if (((z | y | xx) & 1) == 0) {
        b_idx[(z >> 1) * hw2 + (y >> 1) * (W >> 1) + (xx >> 1)] = t;
    } else {
        int cez = (z + 1) >> 1, cey = (y + 1) >> 1, cex = (xx + 1) >> 1;
        int before = cez * hw2;
        if ((z & 1) == 0) { before += cey * (W >> 1); if ((y & 1) == 0) before += cex; }
        a_idx[t - before] = t;
    }
}
__global__ void conv_tok_kernel(int* t) {
    int i = blockIdx.x * 256 + threadIdx.x;
    if (i >= 8 * N2) return;
    int tap = i >> 11, m = i & 2047;
    int kz = tap >> 2, ky = (tap >> 1) & 1, kx = tap & 1;
    int z2 = m >> 8, y2 = (m >> 4) & 15, x2 = m & 15;
    t[i] = (2 * z2 + kz) * (H0 * W0) + (2 * y2 + ky) * W0 + (2 * x2 + kx);
}
__global__ void split3_kernel(const float* __restrict__ s, bf16* p0, bf16* p1, bf16* p2, long n) {
    long i = (long)blockIdx.x * 256 + threadIdx.x;
    if (i >= n) return;
    float v = s[i];
    bf16 h = __float2bfloat16(v); float r = v - __bfloat162float(h);
    bf16 m = __float2bfloat16(r); float r2 = r - __bfloat162float(m);
    p0[i] = h; p1[i] = m; p2[i] = __float2bfloat16(r2);
}
__global__ void split2_kernel(const float* __restrict__ s, bf16* p0, bf16* p1, long n) {
    long i = (long)blockIdx.x * 256 + threadIdx.x;
    if (i >= n) return;
    float v = s[i];
    bf16 h = __float2bfloat16(v);
    p0[i] = h; p1[i] = __float2bfloat16(v - __bfloat162float(h));
}
__global__ void split3_bt_kernel(const float* __restrict__ w, bf16* p0, bf16* p1, bf16* p2) {
    long i = (long)blockIdx.x * 256 + threadIdx.x;
    if (i >= (long)8 * CC * CC) return;
    int tap = (int)(i / (CC * CC));
    int rem = (int)(i - (long)tap * CC * CC);
    int n = rem / CC, k = rem - n * CC;
    float v = w[(long)n * (CC * 8) + k * 8 + tap];
    bf16 h = __float2bfloat16(v); float r = v - __bfloat162float(h);
    bf16 m = __float2bfloat16(r);
    p0[i] = h; p1[i] = m; p2[i] = __float2bfloat16(r - __bfloat162float(m));
}
__global__ void split_qpad_kernel(const float* __restrict__ qm, bf16* p0, bf16* p1) {
    long i = (long)blockIdx.x * 256 + threadIdx.x;
    if (i >= (long)HEADS * MQ * 128) return;
    int h = (int)(i >> 20);
    int m = (int)((i >> 7) & (MQ - 1));
    int k = (int)(i & 127);
    float v = (k < HD) ? qm[(long)m * CC + h * HD + k] : 0.f;
    bf16 hi = __float2bfloat16(v);
    p0[i] = hi; p1[i] = __float2bfloat16(v - __bfloat162float(hi));
}
__global__ void split_kpad_kernel(const float* __restrict__ kvm, bf16* p0, bf16* p1) {
    long i = (long)blockIdx.x * 256 + threadIdx.x;
    if (i >= (long)HEADS * MK * 128) return;
    int h = (int)(i >> 17);
    int m = (int)((i >> 7) & (MK - 1));
    int k = (int)(i & 127);
    float v = (k < HD) ? kvm[(long)m * (2 * CC) + h * HD + k] : 0.f;
    bf16 hi = __float2bfloat16(v);
    p0[i] = hi; p1[i] = __float2bfloat16(v - __bfloat162float(hi));
}
__global__ void split_vT_kernel(const float* __restrict__ kvm, bf16* p0, bf16* p1) {
    long i = (long)blockIdx.x * 256 + threadIdx.x;
    if (i >= (long)HEADS * HD * MK) return;
    int h = (int)(i / (HD * MK));
    int rem = (int)(i - (long)h * HD * MK);
    int n = rem >> 10, k = rem & (MK - 1);
    float v = kvm[(long)k * (2 * CC) + CC + h * HD + n];
    bf16 hi = __float2bfloat16(v);
    p0[i] = hi; p1[i] = __float2bfloat16(v - __bfloat162float(hi));
}

// ---------------- fused LN -> xk, mnk, mk1 ----------------
__global__ void __launch_bounds__(256) ln_norm_kernel(float* __restrict__ xk,
    const float* __restrict__ g, const float* __restrict__ b,
    float* __restrict__ mnk, bf16* __restrict__ mk1)
{
    int row = blockIdx.x;
    float* p = xk + (long)row * CC;
    __shared__ float red[256];
    int tid = threadIdx.x;
    float v0 = p[tid], v1 = p[tid + 256], v2 = p[tid + 512];
    red[tid] = v0 + v1 + v2; __syncthreads();
    for (int off = 128; off; off >>= 1) { if (tid < off) red[tid] += red[tid + off]; __syncthreads(); }
    float mean = red[0] / (float)CC;
    __syncthreads();
    float d0 = v0 - mean, d1 = v1 - mean, d2 = v2 - mean;
    red[tid] = d0 * d0 + d1 * d1 + d2 * d2; __syncthreads();
    for (int off = 128; off; off >>= 1) { if (tid < off) red[tid] += red[tid + off]; __syncthreads(); }
    float var = red[0] / (float)CC;
    float inv = (float)(1.0 / sqrt((double)var + 1e-5));
    __syncthreads();
    float y0 = d0 * inv * g[tid] + b[tid];
    float y1 = d1 * inv * g[tid + 256] + b[tid + 256];
    float y2 = d2 * inv * g[tid + 512] + b[tid + 512];
    p[tid] = y0; p[tid + 256] = y1; p[tid + 512] = y2;
    red[tid] = y0 * y0 + y1 * y1 + y2 * y2; __syncthreads();
    for (int off = 128; off; off >>= 1) { if (tid < off) red[tid] += red[tid + off]; __syncthreads(); }
    float nrm = (float)(1.0 / sqrt((double)red[0]));
    float* q = mnk + (long)row * CC;
    bf16* q1 = mk1 + (long)row * CC;
    float n0 = y0 * nrm, n1 = y1 * nrm, n2 = y2 * nrm;
    q[tid] = n0; q[tid + 256] = n1; q[tid + 512] = n2;
    q1[tid] = __float2bfloat16(n0); q1[tid + 256] = __float2bfloat16(n1); q1[tid + 512] = __float2bfloat16(n2);
}
// fused rownorm -> mnq fp32 + mq1 bf16
__global__ void __launch_bounds__(256) rownorm_cvt_kernel(const float* __restrict__ src,
    float* __restrict__ dst, bf16* __restrict__ dst1)
{
    int row = blockIdx.x;
    const float* p = src + (long)row * CC;
    __shared__ float red[256];
    int tid = threadIdx.x;
    float v0 = p[tid], v1 = p[tid + 256], v2 = p[tid + 512];
    red[tid] = v0 * v0 + v1 * v1 + v2 * v2; __syncthreads();
    for (int off = 128; off; off >>= 1) { if (tid < off) red[tid] += red[tid + off]; __syncthreads(); }
    float inv = (float)(1.0 / sqrt((double)red[0]));
    float* q = dst + (long)row * CC;
    bf16* q1 = dst1 + (long)row * CC;
    float n0 = v0 * inv, n1 = v1 * inv, n2 = v2 * inv;
    q[tid] = n0; q[tid + 256] = n1; q[tid + 512] = n2;
    q1[tid] = __float2bfloat16(n0); q1[tid + 256] = __float2bfloat16(n1); q1[tid + 512] = __float2bfloat16(n2);
}

// ---------------- two-phase BSM scoring ----------------
__global__ void __launch_bounds__(256) rowmax_kernel(const float* __restrict__ S, float* __restrict__ rmax, int ncol) {
    int row = blockIdx.x * 8 + (threadIdx.x >> 5);
    int lane = threadIdx.x & 31;
    const float* p = S + (long)row * ncol;
    float m = -3.4e38f;
    for (int c = lane; c < ncol; c += 32) m = fmaxf(m, p[c]);
    for (int off = 16; off; off >>= 1) m = fmaxf(m, __shfl_xor_sync(0xffffffffu, m, off));
    if (lane == 0) rmax[row] = m;
}
__global__ void __launch_bounds__(256) refine_kernel(
    const float* __restrict__ S, int ncol, const float* __restrict__ mn,
    const int* __restrict__ a_idx, const int* __restrict__ b_idx,
    const float* __restrict__ rmax, u64* __restrict__ key, float margin)
{
    int row = blockIdx.x * 8 + (threadIdx.x >> 5);
    int lane = threadIdx.x & 31;
    const float* p = S + (long)row * ncol;
    float thr = rmax[row] - margin;
    const float* av = mn + (long)a_idx[row] * CC;
    float bestv = -3.4e38f;
    int bestd = 0;
    for (int base = 0; base < ncol; base += 32) {
        float s = p[base + lane];
        unsigned m = __ballot_sync(0xffffffffu, s >= thr);
        while (m) {
            int b = __ffs(m) - 1;
            m &= m - 1;
            int dst = base + b;
            const float* bv = mn + (long)b_idx[dst] * CC;
            float part = 0.f;
            for (int c = lane; c < CC; c += 32) part += av[c] * bv[c];
            for (int off = 16; off; off >>= 1) part += __shfl_xor_sync(0xffffffffu, part, off);
            if (part > bestv) { bestv = part; bestd = dst; }
        }
    }
    if (lane == 0) {
        unsigned u = __float_as_uint(bestv);
        unsigned o = (u & 0x80000000u) ? ~u : (u | 0x80000000u);
        key[row] = ((u64)o << 32) | (unsigned)(~bestd);
    }
}

// ---------------- BSM index machinery ----------------
__global__ void unpack_val_kernel(const u64* __restrict__ key, float* __restrict__ val, int n) {
    int i = blockIdx.x * 256 + threadIdx.x;
    if (i >= n) return;
    uint32_t o = (uint32_t)(key[i] >> 32);
    uint32_t u = (o & 0x80000000u) ? (o ^ 0x80000000u) : ~o;
    val[i] = __uint_as_float(u);
}
__global__ void __launch_bounds__(256) rank_kernel(const float* __restrict__ v, int* __restrict__ perm, int n) {
    int i = blockIdx.x * 256 + threadIdx.x;
    float vi = (i < n) ? v[i] : 0.f;
    int r = 0;
    __shared__ float sv[256];
    for (int base = 0; base < n; base += 256) {
        int j = base + threadIdx.x;
        sv[threadIdx.x] = (j < n) ? v[j] : -3.4e38f;
        __syncthreads();
        int lim = min(256, n - base);
        for (int t = 0; t < lim; t++) {
            float vj = sv[t];
            int j2 = base + t;
            if (vj > vi || (vj == vi && j2 < i)) r++;
        }
        __syncthreads();
    }
    if (i < n) perm[r] = i;
}
__global__ void fill_dst_kernel(const int* __restrict__ perm, const u64* __restrict__ key,
                                int* __restrict__ dst, int* __restrict__ cnt, int R) {
    int e = blockIdx.x * 256 + threadIdx.x;
    if (e >= R) return;
    int s = perm[e];
    uint32_t low = (uint32_t)(key[s]);
    int dd = (int)(~low);
    dst[e] = dd;
    atomicAdd(&cnt[dd], 1);
}
__global__ void __launch_bounds__(256) merge_gather_kernel(const float* __restrict__ src, float* __restrict__ buf,
    const int* __restrict__ a_idx, const int* __restrict__ b_idx,
    const int* __restrict__ perm, int U, int R)
{
    int row = blockIdx.x;
    int tok = (row < U) ? a_idx[perm[R + row]] : b_idx[row - U];
    const float* s = src + (long)tok * CC;
    float* d = buf + (long)row * CC;
    for (int c = threadIdx.x; c < CC; c += 256) d[c] = s[c];
}
__global__ void __launch_bounds__(256) scatter_add_kernel(const float* __restrict__ src, float* __restrict__ buf,
    const int* __restrict__ a_idx, const int* __restrict__ perm, const int* __restrict__ dst, int U)
{
    int e = blockIdx.x;
    int tok = a_idx[perm[e]];
    float* d = buf + (long)(U + dst[e]) * CC;
    const float* s = src + (long)tok * CC;
    for (int c = threadIdx.x; c < CC; c += 256) atomicAdd(&d[c], s[c]);
}
__global__ void __launch_bounds__(256) div_cnt_kernel(float* __restrict__ buf, const int* __restrict__ cnt, int U) {
    int dr = blockIdx.x;
    float cf = (float)cnt[dr];
    float* p = buf + (long)(U + dr) * CC;
    for (int c = threadIdx.x; c < CC; c += 256) p[c] = p[c] / cf;
}

// ---------------- single-pass softmax -> bf16 hi/lo planes ----------------
__global__ void __launch_bounds__(256) softmax_b_kernel(const float* __restrict__ S,
    bf16* __restrict__ sh, bf16* __restrict__ sl)
{
    long row = blockIdx.x;
    const float4 v4 = ((const float4*)(S + row * MK))[threadIdx.x];
    float v[4] = {v4.x, v4.y, v4.z, v4.w};
    __shared__ float red[256];
    int tid = threadIdx.x;
    float m = fmaxf(fmaxf(v[0], v[1]), fmaxf(v[2], v[3]));
    red[tid] = m; __syncthreads();
    for (int off = 128; off; off >>= 1) { if (tid < off) red[tid] = fmaxf(red[tid], red[tid + off]); __syncthreads(); }
    float mx = red[0];
    __syncthreads();
    float e[4], s = 0.f;
#pragma unroll
    for (int i = 0; i < 4; i++) { e[i] = expf(v[i] - mx); s += e[i]; }
    red[tid] = s; __syncthreads();
    for (int off = 128; off; off >>= 1) { if (tid < off) red[tid] += red[tid + off]; __syncthreads(); }
    float inv = 1.0f / red[0];
    uint32_t hp[2], lp[2];
#pragma unroll
    for (int i = 0; i < 2; i++) {
        float a = e[2 * i] * inv, b = e[2 * i + 1] * inv;
        bf16 ha = __float2bfloat16(a), hb = __float2bfloat16(b);
        hp[i] = pkbf(ha, hb);
        lp[i] = pkbf(__float2bfloat16(a - __bfloat162float(ha)),
                     __float2bfloat16(b - __bfloat162float(hb)));
    }
    ((uint2*)(sh + row * MK))[tid] = make_uint2(hp[0], hp[1]);
    ((uint2*)(sl + row * MK))[tid] = make_uint2(lp[0], lp[1]);
}

// ---------------- unmerge ----------------
__global__ void __launch_bounds__(256) unmerge_kernel(const float* __restrict__ proj, float* __restrict__ out,
    const int* __restrict__ a_idx, const int* __restrict__ b_idx,
    const int* __restrict__ perm, const int* __restrict__ dst)
{
    int rid = blockIdx.x;
    int srcrow, tok;
    if (rid < NDQ) { srcrow = UQ + rid; tok = b_idx[rid]; }
    else if (rid < NDQ + UQ) { int u = rid - NDQ; srcrow = u; tok = a_idx[perm[RQ + u]]; }
    else { int e = rid - (NDQ + UQ); srcrow = UQ + dst[e]; tok = a_idx[perm[e]]; }
    const float* s = proj + (long)srcrow * CC;
    float* d = out + (long)tok * CC;
    for (int c = threadIdx.x; c < CC; c += 256) d[c] = s[c];
}

// ---------------- host launcher ----------------
#define SM_NPR1 (2 * 2 * 16384)
#define SM_NPR3 (2 * 4 * 16384)
#define SM_NPR6 (2 * 6 * 16384)

extern "C" void kernel_launch(void* const* d_in, const int* in_sizes, int n_in,
                              void* d_out, int out_size)
{
    (void)in_sizes; (void)n_in; (void)out_size;
    const float* x   = (const float*)d_in[0];
    const float* srw = (const float*)d_in[1];
    const float* srb = (const float*)d_in[2];
    const float* lng = (const float*)d_in[3];
    const float* lnb = (const float*)d_in[4];
    const float* Wq  = (const float*)d_in[5];
    const float* Wkv = (const float*)d_in[6];
    const float* Wp  = (const float*)d_in[7];
    const float* bp  = (const float*)d_in[8];
    float* out = (float*)d_out;

    cudaFuncSetAttribute(mmg<6>, cudaFuncAttributeMaxDynamicSharedMemorySize, SM_NPR6);
    cudaFuncSetAttribute(mmg<3>, cudaFuncAttributeMaxDynamicSharedMemorySize, SM_NPR3);
    cudaFuncSetAttribute(mmg<1>, cudaFuncAttributeMaxDynamicSharedMemorySize, SM_NPR1);

    float *xk, *mnq, *mnk, *nvq, *nvk, *rmax, *xq, *xkm, *qm, *kvm, *S, *ao, *proj;
    u64 *keyq, *keyk;
    int *permq, *permk, *dstq, *dstk, *cntq, *cntk, *aq, *bq, *ak, *bk, *ctok;
    bf16 *x3, *bt3, *mq1, *mk1, *xq2, *xkm2, *wq2, *wkv2, *wp2, *qp2, *kp2, *vp2, *ao2, *sh, *sl;
    cudaGetSymbolAddress((void**)&xk, g_xk);
    cudaGetSymbolAddress((void**)&mnq, g_mnq);
    cudaGetSymbolAddress((void**)&mnk, g_mnk);
    cudaGetSymbolAddress((void**)&nvq, g_nvq);
    cudaGetSymbolAddress((void**)&nvk, g_nvk);
    cudaGetSymbolAddress((void**)&rmax, g_rmax);
    cudaGetSymbolAddress((void**)&xq, g_xq);
    cudaGetSymbolAddress((void**)&xkm, g_xkm);
    cudaGetSymbolAddress((void**)&qm, g_qm);
    cudaGetSymbolAddress((void**)&kvm, g_kvm);
    cudaGetSymbolAddress((void**)&S, g_S);
    cudaGetSymbolAddress((void**)&ao, g_ao);
    cudaGetSymbolAddress((void**)&proj, g_proj);
    cudaGetSymbolAddress((void**)&keyq, g_keyq);
    cudaGetSymbolAddress((void**)&keyk, g_keyk);
    cudaGetSymbolAddress((void**)&permq, g_permq);
    cudaGetSymbolAddress((void**)&permk, g_permk);
    cudaGetSymbolAddress((void**)&dstq, g_dstq);
    cudaGetSymbolAddress((void**)&dstk, g_dstk);
    cudaGetSymbolAddress((void**)&cntq, g_cntq);
    cudaGetSymbolAddress((void**)&cntk, g_cntk);
    cudaGetSymbolAddress((void**)&aq, g_aq);
    cudaGetSymbolAddress((void**)&bq, g_bq);
    cudaGetSymbolAddress((void**)&ak, g_ak);
    cudaGetSymbolAddress((void**)&bk, g_bk);
    cudaGetSymbolAddress((void**)&ctok, g_ctok);
    cudaGetSymbolAddress((void**)&x3, g_x3);
    cudaGetSymbolAddress((void**)&bt3, g_bt3);
    cudaGetSymbolAddress((void**)&mq1, g_mq1);
    cudaGetSymbolAddress((void**)&mk1, g_mk1);
    cudaGetSymbolAddress((void**)&xq2, g_xq2);
    cudaGetSymbolAddress((void**)&xkm2, g_xkm2);
    cudaGetSymbolAddress((void**)&wq2, g_wq2);
    cudaGetSymbolAddress((void**)&wkv2, g_wkv2);
    cudaGetSymbolAddress((void**)&wp2, g_wp2);
    cudaGetSymbolAddress((void**)&qp2, g_qp2);
    cudaGetSymbolAddress((void**)&kp2, g_kp2);
    cudaGetSymbolAddress((void**)&vp2, g_vp2);
    cudaGetSymbolAddress((void**)&ao2, g_ao2);
    cudaGetSymbolAddress((void**)&sh, g_sh);
    cudaGetSymbolAddress((void**)&sl, g_sl);

    const long PXQ = (long)NQ * CC;
    const long PBT = (long)8 * CC * CC;
    const long PQ2 = (long)MQ * CC;
    const long PK2 = (long)MK * CC;
    const long PWQ = (long)CC * CC;
    const long PWKV = (long)2 * CC * CC;
    const long PQP = (long)HEADS * MQ * 128;
    const long PKP = (long)HEADS * MK * 128;
    const long PVP = (long)HEADS * HD * MK;
    float* Skv = S + (long)NAQ * NDQ;

    // 1-3: conv prerequisites
    split3_kernel<<<(int)((PXQ + 255) / 256), 256>>>(x, x3, x3 + PXQ, x3 + 2 * PXQ, PXQ);
    split3_bt_kernel<<<(int)((PBT + 255) / 256), 256>>>(srw, bt3, bt3 + PBT, bt3 + 2 * PBT);
    conv_tok_kernel<<<(8 * N2 + 255) / 256, 256>>>(ctok);
    // 4: conv GEMM (profiled slot)
    mmg<6><<<dim3(CC / 128, N2 / 128, 1), 256, SM_NPR6>>>(
        x3, x3 + PXQ, x3 + 2 * PXQ, CC, 0,
        bt3, bt3 + PBT, bt3 + 2 * PBT, CC, 0, (long)CC * CC,
        xk, CC, 0, srb, 1.f, CC, CC, 8, ctok, N2, nullptr);
    // 5: fused LN + rownorm + cvt (kv metric)
    ln_norm_kernel<<<N2, 256>>>(xk, lng, lnb, mnk, mk1);
    // index tables
    build_idx_kernel<<<(NQ + 255) / 256, 256>>>(D0, H0, W0, aq, bq);
    build_idx_kernel<<<(N2 + 255) / 256, 256>>>(D0 / 2, H0 / 2, W0 / 2, ak, bk);

    // ---- q-side BSM ----
    rownorm_cvt_kernel<<<NQ, 256>>>(x, mnq, mq1);
    mmg<1><<<dim3(NDQ / 128, NAQ / 128, 1), 256, SM_NPR1>>>(
        mq1, nullptr, nullptr, CC, 0,
        mq1, nullptr, nullptr, CC, 0, 0,
        S, NDQ, 0, nullptr, 1.f, NDQ, CC, 1, aq, 0, bq);
    rowmax_kernel<<<NAQ / 8, 256>>>(S, rmax, NDQ);
    refine_kernel<<<NAQ / 8, 256>>>(S, NDQ, mnq, aq, bq, rmax, keyq, 2e-3f);
    unpack_val_kernel<<<(NAQ + 255) / 256, 256>>>(keyq, nvq, NAQ);
    rank_kernel<<<NAQ / 256, 256>>>(nvq, permq, NAQ);
    set_int_kernel<<<(NDQ + 255) / 256, 256>>>(cntq, NDQ, 1);
    fill_dst_kernel<<<(RQ + 255) / 256, 256>>>(permq, keyq, dstq, cntq, RQ);
    merge_gather_kernel<<<MQ, 256>>>(x, xq, aq, bq, permq, UQ, RQ);
    scatter_add_kernel<<<RQ, 256>>>(x, xq, aq, permq, dstq, UQ);
    div_cnt_kernel<<<NDQ, 256>>>(xq, cntq, UQ);

    // ---- kv-side BSM ----
    mmg<1><<<dim3(NDK / 128, NAK / 128, 1), 256, SM_NPR1>>>(
        mk1, nullptr, nullptr, CC, 0,
        mk1, nullptr, nullptr, CC, 0, 0,
        Skv, NDK, 0, nullptr, 1.f, NDK, CC, 1, ak, 0, bk);
    rowmax_kernel<<<NAK / 8, 256>>>(Skv, rmax, NDK);
    refine_kernel<<<NAK / 8, 256>>>(Skv, NDK, mnk, ak, bk, rmax, keyk, 2e-3f);
    unpack_val_kernel<<<(NAK + 255) / 256, 256>>>(keyk, nvk, NAK);
    rank_kernel<<<NAK / 256, 256>>>(nvk, permk, NAK);
    set_int_kernel<<<1, 256>>>(cntk, NDK, 1);
    fill_dst_kernel<<<(RK + 255) / 256, 256>>>(permk, keyk, dstk, cntk, RK);
    merge_gather_kernel<<<MK, 256>>>(xk, xkm, ak, bk, permk, UK, RK);
    scatter_add_kernel<<<RK, 256>>>(xk, xkm, ak, permk, dstk, UK);
    div_cnt_kernel<<<NDK, 256>>>(xkm, cntk, UK);

    // ---- projections (3-product) ----
    split2_kernel<<<(int)((PWQ + 255) / 256), 256>>>(Wq, wq2, wq2 + PWQ, PWQ);
    split2_kernel<<<(int)((PWKV + 255) / 256), 256>>>(Wkv, wkv2, wkv2 + PWKV, PWKV);
    split2_kernel<<<(int)((PWQ + 255) / 256), 256>>>(Wp, wp2, wp2 + PWQ, PWQ);
    split2_kernel<<<(int)((PQ2 + 255) / 256), 256>>>(xq, xq2, xq2 + PQ2, PQ2);
    split2_kernel<<<(int)((PK2 + 255) / 256), 256>>>(xkm, xkm2, xkm2 + PK2, PK2);
    mmg<3><<<dim3(CC / 128, MQ / 128, 1), 256, SM_NPR3>>>(
        xq2, xq2 + PQ2, nullptr, CC, 0,
        wq2, wq2 + PWQ, nullptr, CC, 0, 0,
        qm, CC, 0, nullptr, 1.f, CC, CC, 1, nullptr, 0, nullptr);
    mmg<3><<<dim3(2 * CC / 128, MK / 128, 1), 256, SM_NPR3>>>(
        xkm2, xkm2 + PK2, nullptr, CC, 0,
        wkv2, wkv2 + PWKV, nullptr, CC, 0, 0,
        kvm, 2 * CC, 0, nullptr, 1.f, 2 * CC, CC, 1, nullptr, 0, nullptr);

    // ---- head prep (padded K=128) ----
    split_qpad_kernel<<<(int)((PQP + 255) / 256), 256>>>(qm, qp2, qp2 + PQP);
    split_kpad_kernel<<<(int)((PKP + 255) / 256), 256>>>(kvm, kp2, kp2 + PKP);
    split_vT_kernel<<<(int)((PVP + 255) / 256), 256>>>(kvm, vp2, vp2 + PVP);

    // ---- attention ----
    float scl = 1.0f / sqrtf((float)HD);
    mmg<3><<<dim3(MK / 128, MQ / 128, HEADS), 256, SM_NPR3>>>(
        qp2, qp2 + PQP, nullptr, 128, (long)MQ * 128,
        kp2, kp2 + PKP, nullptr, 128, (long)MK * 128, 0,
        S, MK, (long)MQ * MK, nullptr, scl, MK, 128, 1, nullptr, 0, nullptr);
    softmax_b_kernel<<<HEADS * MQ, 256>>>(S, sh, sl);
    mmg<3><<<dim3(1, MQ / 128, HEADS), 256, SM_NPR3>>>(
        sh, sl, nullptr, MK, (long)MQ * MK,
        vp2, vp2 + PVP, nullptr, MK, (long)HD * MK, 0,
        ao, CC, HD, nullptr, 1.f, HD, MK, 1, nullptr, 0, nullptr);

    // ---- output projection + unmerge ----
    split2_kernel<<<(int)((PQ2 + 255) / 256), 256>>>(ao, ao2, ao2 + PQ2, PQ2);
    mmg<3><<<dim3(CC / 128, MQ / 128, 1), 256, SM_NPR3>>>(
        ao2, ao2 + PQ2, nullptr, CC, 0,
        wp2, wp2 + PWQ, nullptr, CC, 0, 0,
        proj, CC, 0, bp, 1.f, CC, CC, 1, nullptr, 0, nullptr);
    unmerge_kernel<<<NQ, 256>>>(proj, out, aq, bq, permq, dstq);
}

// round 8
// speedup vs baseline: 1.9910x; 1.0931x over previous
#include <cuda_runtime.h>
#include <cuda_bf16.h>
#include <math.h>
#include <stdint.h>

// ---------------- static problem sizes ----------------
#define CC    768
#define D0    16
#define H0    32
#define W0    32
#define NQ    16384
#define NDQ   2048
#define NAQ   14336
#define RQ    8192
#define UQ    6144
#define MQ    8192
#define N2    2048
#define NDK   256
#define NAK   1792
#define RK    1024
#define UK    768
#define MK    1024
#define HEADS 8
#define HD    96

typedef __nv_bfloat16 bf16;
typedef unsigned long long u64;

// ---------------- device scratch ----------------
__device__ float g_xk[N2 * CC];
__device__ float g_mnq[NQ * CC];
__device__ float g_mnk[N2 * CC];
__device__ u64   g_keyq[NAQ];
__device__ u64   g_keyk[NAK];
__device__ float g_nvq[NAQ];
__device__ float g_nvk[NAK];
__device__ float g_rmax[NAQ];
__device__ int g_permq[NAQ];
__device__ int g_permk[NAK];
__device__ int g_dstq[RQ];
__device__ int g_dstk[RK];
__device__ int g_cntq[NDQ];
__device__ int g_cntk[NDK];
__device__ int g_aq[NAQ];
__device__ int g_bq[NDQ];
__device__ int g_ak[NAK];
__device__ int g_bk[NDK];
__device__ int g_ctok[8 * N2];
__device__ float g_xq[MQ * CC];
__device__ float g_xkm[MK * CC];
__device__ float g_qm[MQ * CC];
__device__ float g_kvm[MK * 2 * CC];
__device__ float g_S[(long)HEADS * MQ * MK];
__device__ float g_ao[MQ * CC];
__device__ float g_proj[MQ * CC];

// bf16 planes
__device__ bf16 g_x3[3][NQ * CC];
__device__ bf16 g_bt3[3][8 * CC * CC];
__device__ bf16 g_mq1[NQ * CC];
__device__ bf16 g_mk1[N2 * CC];
__device__ bf16 g_xq2[2][MQ * CC];
__device__ bf16 g_xkm2[2][MK * CC];
__device__ bf16 g_wq2[2][CC * CC];
__device__ bf16 g_wkv2[2][2 * CC * CC];
__device__ bf16 g_wp2[2][CC * CC];
__device__ bf16 g_qp2[2][HEADS * MQ * 128];
__device__ bf16 g_kp2[2][HEADS * MK * 128];
__device__ bf16 g_vp2[2][HEADS * HD * MK];
__device__ bf16 g_ao2[2][MQ * CC];
__device__ bf16 g_sh[(long)HEADS * MQ * MK];
__device__ bf16 g_sl[(long)HEADS * MQ * MK];

__device__ __forceinline__ uint32_t smem_u32(const void* p) {
    uint32_t a;
    asm("{ .reg .u64 t; cvta.to.shared.u64 t, %1; cvt.u32.u64 %0, t; }" : "=r"(a) : "l"(p));
    return a;
}
__device__ __forceinline__ uint32_t pkbf(bf16 a, bf16 b) {
    return (uint32_t)__bfloat16_as_ushort(a) | ((uint32_t)__bfloat16_as_ushort(b) << 16);
}
#define SWZ(o) ((o) ^ (((o) >> 3) & 0x70))
#define MMA16816(d, a, b0v, b1v) \
    asm volatile("mma.sync.aligned.m16n8k16.row.col.f32.bf16.bf16.f32 " \
        "{%0,%1,%2,%3}, {%4,%5,%6,%7}, {%8,%9}, {%0,%1,%2,%3};" \
        : "+f"((d)[0]), "+f"((d)[1]), "+f"((d)[2]), "+f"((d)[3]) \
        : "r"((a)[0]), "r"((a)[1]), "r"((a)[2]), "r"((a)[3]), "r"(b0v), "r"(b1v))
#define LDSM4(r, a) \
    asm volatile("ldmatrix.sync.aligned.m8n8.x4.shared.b16 {%0,%1,%2,%3}, [%4];" \
        : "=r"((r)[0]), "=r"((r)[1]), "=r"((r)[2]), "=r"((r)[3]) : "r"(a))
#define CPA(dst, src, sz) \
    asm volatile("cp.async.cg.shared.global [%0], [%1], 16, %2;" :: "r"(dst), "l"(src), "r"(sz) : "memory")
#define CPCOMMIT() asm volatile("cp.async.commit_group;" ::: "memory")
#define CPWAIT1()  asm volatile("cp.async.wait_group 1;" ::: "memory")

// ---------------- pipelined ldmatrix mma.sync split-bf16 GEMM ----------------
// C[M,N] = scale * A[M,K] @ B[N,K]^T (+bias), over ntap segments.
// Block 128 x TN, k-tile 64, 3-stage cp.async pipeline (1 sync/chunk),
// 16 warps (4m x 4n), warp tile 32 x (TN/4).
template <int NPR, int TN>
__global__ void __launch_bounds__(512) mmg(
    const bf16* A0, const bf16* A1, const bf16* A2, long lda, long ahs,
    const bf16* B0, const bf16* B1, const bf16* B2, long ldb, long bhs, long bseg,
    float* C, long ldc, long chs, const float* bias, float scale,
    int N, int K, int ntap, const int* gA, int gAs, const int* gB)
{
    constexpr int nA = (NPR == 6) ? 3 : (NPR == 3) ? 2 : 1;
    constexpr int nB = nA;
    constexpr int PLA = 16384;         // 128 rows x 128 B
    constexpr int PLB = TN * 128;
    constexpr int STG = nA * PLA + nB * PLB;
    constexpr int NJ = TN / 32;        // n-tiles of 8 per warp
    extern __shared__ char sm[];
    const uint32_t su = smem_u32(sm);

    const int tid = threadIdx.x, lane = tid & 31, wid = tid >> 5;
    const int wm = wid >> 2, wn = wid & 3;
    const int m0 = blockIdx.y * 128, n0 = blockIdx.x * TN, z = blockIdx.z;
    const int lq = lane >> 2, lr = lane & 3;

    // loaders
    const int lrA = tid >> 2, secA = tid & 3;                     // 2x16B per plane
    const int lrB = (TN == 128) ? (tid >> 2) : (tid >> 3);
    const int secB = (TN == 128) ? (tid & 3) : (tid & 7);
    const int nrow = n0 + lrB;
    const bool bval = nrow < N;
    const long brow = bval ? (gB ? (long)gB[nrow] : (long)nrow) : 0;
    const uint32_t bsz = bval ? 16u : 0u;

    const uint32_t dA0 = SWZ((uint32_t)(lrA * 128 + secA * 32));
    const uint32_t dA1 = SWZ((uint32_t)(lrA * 128 + secA * 32 + 16));
    const uint32_t dB0 = (TN == 128) ? SWZ((uint32_t)(lrB * 128 + secB * 32))
                                     : SWZ((uint32_t)(lrB * 128 + secB * 16));
    const uint32_t dB1 = (TN == 128) ? SWZ((uint32_t)(lrB * 128 + secB * 32 + 16)) : 0u;

    const int kc = K >> 6;
    const int nch = ntap * kc;
    const bf16* Ap[3] = {A0, A1, A2};
    const bf16* Bp[3] = {B0, B1, B2};

    float acc[2][NJ][4];
#pragma unroll
    for (int i = 0; i < 2; i++)
#pragma unroll
        for (int j = 0; j < NJ; j++)
#pragma unroll
            for (int t = 0; t < 4; t++) acc[i][j][t] = 0.f;

    auto issue = [&](int c) {
        const int stg = c % 3;
        const uint32_t sb = su + stg * STG;
        const int tap = c / kc;
        const int k0 = (c - tap * kc) << 6;
        const long arow = gA ? (long)gA[tap * gAs + m0 + lrA] : (long)(m0 + lrA);
#pragma unroll
        for (int p = 0; p < nA; p++) {
            const bf16* s0 = Ap[p] + (long)z * ahs + arow * lda + k0 + secA * 16;
            CPA(sb + p * PLA + dA0, s0, 16u);
            CPA(sb + p * PLA + dA1, s0 + 8, 16u);
        }
#pragma unroll
        for (int p = 0; p < nB; p++) {
            const bf16* s0 = Bp[p] + (long)z * bhs + (long)tap * bseg + brow * ldb + k0
                           + secB * (TN == 128 ? 16 : 8);
            CPA(sb + nA * PLA + p * PLB + dB0, s0, bsz);
            if (TN == 128) CPA(sb + nA * PLA + p * PLB + dB1, s0 + 8, bsz);
        }
        CPCOMMIT();
    };

    auto compute = [&](int stg) {
        const uint32_t sb = su + stg * STG;
        const int pa6[6] = {0, 0, 1, 1, 0, 2}, pb6[6] = {0, 1, 0, 1, 2, 0};
#pragma unroll
        for (int ks = 0; ks < 4; ks++) {
            uint32_t af[nA][2][4];
#pragma unroll
            for (int p = 0; p < nA; p++)
#pragma unroll
                for (int i = 0; i < 2; i++) {
                    uint32_t off = (uint32_t)((wm * 32 + i * 16 + (lane & 15)) * 128
                                              + ks * 32 + ((lane >> 4) << 4));
                    LDSM4(af[p][i], sb + p * PLA + SWZ(off));
                }
            uint32_t bl[nB][NJ], bh[nB][NJ];
            if constexpr (TN == 128) {
#pragma unroll
                for (int p = 0; p < nB; p++) {
                    uint32_t r0[4], r1[4];
                    uint32_t off0 = (uint32_t)((wn * 32 + (lane >> 3) * 8 + (lane & 7)) * 128 + ks * 32);
                    LDSM4(r0, sb + nA * PLA + p * PLB + SWZ(off0));
                    LDSM4(r1, sb + nA * PLA + p * PLB + SWZ(off0 + 16));
#pragma unroll
                    for (int j = 0; j < 4; j++) { bl[p][j] = r0[j]; bh[p][j] = r1[j]; }
                }
            } else {
#pragma unroll
                for (int p = 0; p < nB; p++) {
                    uint32_t r[4];
                    const int tileB = (lane >> 3) & 1, khB = lane >> 4;
                    uint32_t off = (uint32_t)((wn * 16 + tileB * 8 + (lane & 7)) * 128
                                              + ks * 32 + khB * 16);
                    LDSM4(r, sb + nA * PLA + p * PLB + SWZ(off));
                    bl[p][0] = r[0]; bl[p][1] = r[1]; bh[p][0] = r[2]; bh[p][1] = r[3];
                }
            }
#pragma unroll
            for (int pr = 0; pr < NPR; pr++) {
                const int pA = (NPR == 1) ? 0 : pa6[pr];
                const int pB = (NPR == 1) ? 0 : pb6[pr];
#pragma unroll
                for (int i = 0; i < 2; i++)
#pragma unroll
                    for (int j = 0; j < NJ; j++)
                        MMA16816(acc[i][j], af[pA][i], bl[pB][j], bh[pB][j]);
            }
        }
    };

    issue(0);
    for (int c = 0; c < nch; c++) {
        if (c + 1 < nch) issue(c + 1);
        else CPCOMMIT();       // keep one commit per iteration -> wait_group 1 exact
        CPWAIT1();
        __syncthreads();
        compute(c % 3);
    }

    // ---- epilogue ----
#pragma unroll
    for (int i = 0; i < 2; i++) {
        const int r = m0 + wm * 32 + i * 16 + lq;
#pragma unroll
        for (int j = 0; j < NJ; j++) {
            const int cb = n0 + wn * (TN / 4) + j * 8 + lr * 2;
            if (cb < N) {
                float bb0 = bias ? bias[cb] : 0.f;
                float bb1 = bias ? bias[cb + 1] : 0.f;
                float* p0 = C + (long)z * chs + (long)r * ldc + cb;
                float* p1 = C + (long)z * chs + (long)(r + 8) * ldc + cb;
                p0[0] = acc[i][j][0] * scale + bb0;
                p0[1] = acc[i][j][1] * scale + bb1;
                p1[0] = acc[i][j][2] * scale + bb0;
                p1[1] = acc[i][j][3] * scale + bb1;
            }
        }
    }
}

// ---------------- utility / prep kernels ----------------
__global__ void set_int_kernel(int* p, int n, int v) {
    int i = blockIdx.x * 256 + threadIdx.x;
    if (i < n) p[i] = v;
}
__global__ void build_idx_kernel(int D, int H, int W, int* a_idx, int* b_idx) {
    int n = D * H * W;
    int t = blockIdx.x * 256 + threadIdx.x;
    if (t >= n) return;
    int z = t / (H * W), y = (t / W) % H, xx = t % W;
    int hw2 = (H >> 1) * (W >> 1);
    if (((z | y | xx) & 1) == 0) {
        b_idx[(z >> 1) * hw2 + (y >> 1) * (W >> 1) + (xx >> 1)] = t;
    } else {
        int cez = (z + 1) >> 1, cey = (y + 1) >> 1, cex = (xx + 1) >> 1;
        int before = cez * hw2;
        if ((z & 1) == 0) { before += cey * (W >> 1); if ((y & 1) == 0) before += cex; }
        a_idx[t - before] = t;
    }
}
__global__ void conv_tok_kernel(int* t) {
    int i = blockIdx.x * 256 + threadIdx.x;
    if (i >= 8 * N2) return;
    int tap = i >> 11, m = i & 2047;
    int kz = tap >> 2, ky = (tap >> 1) & 1, kx = tap & 1;
    int z2 = m >> 8, y2 = (m >> 4) & 15, x2 = m & 15;
    t[i] = (2 * z2 + kz) * (H0 * W0) + (2 * y2 + ky) * W0 + (2 * x2 + kx);
}
__global__ void split3_kernel(const float* __restrict__ s, bf16* p0, bf16* p1, bf16* p2, long n) {
    long i = (long)blockIdx.x * 256 + threadIdx.x;
    if (i >= n) return;
    float v = s[i];
    bf16 h = __float2bfloat16(v); float r = v - __bfloat162float(h);
    bf16 m = __float2bfloat16(r); float r2 = r - __bfloat162float(m);
    p0[i] = h; p1[i] = m; p2[i] = __float2bfloat16(r2);
}
__global__ void split2_kernel(const float* __restrict__ s, bf16* p0, bf16* p1, long n) {
    long i = (long)blockIdx.x * 256 + threadIdx.x;
    if (i >= n) return;
    float v = s[i];
    bf16 h = __float2bfloat16(v);
    p0[i] = h; p1[i] = __float2bfloat16(v - __bfloat162float(h));
}
__global__ void split3_bt_kernel(const float* __restrict__ w, bf16* p0, bf16* p1, bf16* p2) {
    long i = (long)blockIdx.x * 256 + threadIdx.x;
    if (i >= (long)8 * CC * CC) return;
    int tap = (int)(i / (CC * CC));
    int rem = (int)(i - (long)tap * CC * CC);
    int n = rem / CC, k = rem - n * CC;
    float v = w[(long)n * (CC * 8) + k * 8 + tap];
    bf16 h = __float2bfloat16(v); float r = v - __bfloat162float(h);
    bf16 m = __float2bfloat16(r);
    p0[i] = h; p1[i] = m; p2[i] = __float2bfloat16(r - __bfloat162float(m));
}
__global__ void split_qpad_kernel(const float* __restrict__ qm, bf16* p0, bf16* p1) {
    long i = (long)blockIdx.x * 256 + threadIdx.x;
    if (i >= (long)HEADS * MQ * 128) return;
    int h = (int)(i >> 20);
    int m = (int)((i >> 7) & (MQ - 1));
    int k = (int)(i & 127);
    float v = (k < HD) ? qm[(long)m * CC + h * HD + k] : 0.f;
    bf16 hi = __float2bfloat16(v);
    p0[i] = hi; p1[i] = __float2bfloat16(v - __bfloat162float(hi));
}
__global__ void split_kpad_kernel(const float* __restrict__ kvm, bf16* p0, bf16* p1) {
    long i = (long)blockIdx.x * 256 + threadIdx.x;
    if (i >= (long)HEADS * MK * 128) return;
    int h = (int)(i >> 17);
    int m = (int)((i >> 7) & (MK - 1));
    int k = (int)(i & 127);
    float v = (k < HD) ? kvm[(long)m * (2 * CC) + h * HD + k] : 0.f;
    bf16 hi = __float2bfloat16(v);
    p0[i] = hi; p1[i] = __float2bfloat16(v - __bfloat162float(hi));
}
__global__ void split_vT_kernel(const float* __restrict__ kvm, bf16* p0, bf16* p1) {
    long i = (long)blockIdx.x * 256 + threadIdx.x;
    if (i >= (long)HEADS * HD * MK) return;
    int h = (int)(i / (HD * MK));
    int rem = (int)(i - (long)h * HD * MK);
    int n = rem >> 10, k = rem & (MK - 1);
    float v = kvm[(long)k * (2 * CC) + CC + h * HD + n];
    bf16 hi = __float2bfloat16(v);
    p0[i] = hi; p1[i] = __float2bfloat16(v - __bfloat162float(hi));
}

// ---------------- fused LN -> xk, mnk, mk1 ----------------
__global__ void __launch_bounds__(256) ln_norm_kernel(float* __restrict__ xk,
    const float* __restrict__ g, const float* __restrict__ b,
    float* __restrict__ mnk, bf16* __restrict__ mk1)
{
    int row = blockIdx.x;
    float* p = xk + (long)row * CC;
    __shared__ float red[256];
    int tid = threadIdx.x;
    float v0 = p[tid], v1 = p[tid + 256], v2 = p[tid + 512];
    red[tid] = v0 + v1 + v2; __syncthreads();
    for (int off = 128; off; off >>= 1) { if (tid < off) red[tid] += red[tid + off]; __syncthreads(); }
    float mean = red[0] / (float)CC;
    __syncthreads();
    float d0 = v0 - mean, d1 = v1 - mean, d2 = v2 - mean;
    red[tid] = d0 * d0 + d1 * d1 + d2 * d2; __syncthreads();
    for (int off = 128; off; off >>= 1) { if (tid < off) red[tid] += red[tid + off]; __syncthreads(); }
    float var = red[0] / (float)CC;
    float inv = (float)(1.0 / sqrt((double)var + 1e-5));
    __syncthreads();
    float y0 = d0 * inv * g[tid] + b[tid];
    float y1 = d1 * inv * g[tid + 256] + b[tid + 256];
    float y2 = d2 * inv * g[tid + 512] + b[tid + 512];
    p[tid] = y0; p[tid + 256] = y1; p[tid + 512] = y2;
    red[tid] = y0 * y0 + y1 * y1 + y2 * y2; __syncthreads();
    for (int off = 128; off; off >>= 1) { if (tid < off) red[tid] += red[tid + off]; __syncthreads(); }
    float nrm = (float)(1.0 / sqrt((double)red[0]));
    float* q = mnk + (long)row * CC;
    bf16* q1 = mk1 + (long)row * CC;
    float n0 = y0 * nrm, n1 = y1 * nrm, n2 = y2 * nrm;
    q[tid] = n0; q[tid + 256] = n1; q[tid + 512] = n2;
    q1[tid] = __float2bfloat16(n0); q1[tid + 256] = __float2bfloat16(n1); q1[tid + 512] = __float2bfloat16(n2);
}
__global__ void __launch_bounds__(256) rownorm_cvt_kernel(const float* __restrict__ src,
    float* __restrict__ dst, bf16* __restrict__ dst1)
{
    int row = blockIdx.x;
    const float* p = src + (long)row * CC;
    __shared__ float red[256];
    int tid = threadIdx.x;
    float v0 = p[tid], v1 = p[tid + 256], v2 = p[tid + 512];
    red[tid] = v0 * v0 + v1 * v1 + v2 * v2; __syncthreads();
    for (int off = 128; off; off >>= 1) { if (tid < off) red[tid] += red[tid + off]; __syncthreads(); }
    float inv = (float)(1.0 / sqrt((double)red[0]));
    float* q = dst + (long)row * CC;
    bf16* q1 = dst1 + (long)row * CC;
    float n0 = v0 * inv, n1 = v1 * inv, n2 = v2 * inv;
    q[tid] = n0; q[tid + 256] = n1; q[tid + 512] = n2;
    q1[tid] = __float2bfloat16(n0); q1[tid + 256] = __float2bfloat16(n1); q1[tid + 512] = __float2bfloat16(n2);
}

// ---------------- two-phase BSM scoring ----------------
__global__ void __launch_bounds__(256) rowmax_kernel(const float* __restrict__ S, float* __restrict__ rmax, int ncol) {
    int row = blockIdx.x * 8 + (threadIdx.x >> 5);
    int lane = threadIdx.x & 31;
    const float* p = S + (long)row * ncol;
    float m = -3.4e38f;
    for (int c = lane; c < ncol; c += 32) m = fmaxf(m, p[c]);
    for (int off = 16; off; off >>= 1) m = fmaxf(m, __shfl_xor_sync(0xffffffffu, m, off));
    if (lane == 0) rmax[row] = m;
}
__global__ void __launch_bounds__(256) refine_kernel(
    const float* __restrict__ S, int ncol, const float* __restrict__ mn,
    const int* __restrict__ a_idx, const int* __restrict__ b_idx,
    const float* __restrict__ rmax, u64* __restrict__ key, float margin)
{
    int row = blockIdx.x * 8 + (threadIdx.x >> 5);
    int lane = threadIdx.x & 31;
    const float* p = S + (long)row * ncol;
    float thr = rmax[row] - margin;
    const float* av = mn + (long)a_idx[row] * CC;
    float bestv = -3.4e38f;
    int bestd = 0;
    for (int base = 0; base < ncol; base += 32) {
        float s = p[base + lane];
        unsigned m = __ballot_sync(0xffffffffu, s >= thr);
        while (m) {
            int b = __ffs(m) - 1;
            m &= m - 1;
            int dst = base + b;
            const float* bv = mn + (long)b_idx[dst] * CC;
            float part = 0.f;
            for (int c = lane; c < CC; c += 32) part += av[c] * bv[c];
            for (int off = 16; off; off >>= 1) part += __shfl_xor_sync(0xffffffffu, part, off);
            if (part > bestv) { bestv = part; bestd = dst; }
        }
    }
    if (lane == 0) {
        unsigned u = __float_as_uint(bestv);
        unsigned o = (u & 0x80000000u) ? ~u : (u | 0x80000000u);
        key[row] = ((u64)o << 32) | (unsigned)(~bestd);
    }
}

// ---------------- BSM index machinery ----------------
__global__ void unpack_val_kernel(const u64* __restrict__ key, float* __restrict__ val, int n) {
    int i = blockIdx.x * 256 + threadIdx.x;
    if (i >= n) return;
    uint32_t o = (uint32_t)(key[i] >> 32);
    uint32_t u = (o & 0x80000000u) ? (o ^ 0x80000000u) : ~o;
    val[i] = __uint_as_float(u);
}
__global__ void __launch_bounds__(256) rank_kernel(const float* __restrict__ v, int* __restrict__ perm, int n) {
    int i = blockIdx.x * 256 + threadIdx.x;
    float vi = (i < n) ? v[i] : 0.f;
    int r = 0;
    __shared__ float sv[256];
    for (int base = 0; base < n; base += 256) {
        int j = base + threadIdx.x;
        sv[threadIdx.x] = (j < n) ? v[j] : -3.4e38f;
        __syncthreads();
        int lim = min(256, n - base);
        for (int t = 0; t < lim; t++) {
            float vj = sv[t];
            int j2 = base + t;
            if (vj > vi || (vj == vi && j2 < i)) r++;
        }
        __syncthreads();
    }
    if (i < n) perm[r] = i;
}
__global__ void fill_dst_kernel(const int* __restrict__ perm, const u64* __restrict__ key,
                                int* __restrict__ dst, int* __restrict__ cnt, int R) {
    int e = blockIdx.x * 256 + threadIdx.x;
    if (e >= R) return;
    int s = perm[e];
    uint32_t low = (uint32_t)(key[s]);
    int dd = (int)(~low);
    dst[e] = dd;
    atomicAdd(&cnt[dd], 1);
}
__global__ void __launch_bounds__(256) merge_gather_kernel(const float* __restrict__ src, float* __restrict__ buf,
    const int* __restrict__ a_idx, const int* __restrict__ b_idx,
    const int* __restrict__ perm, int U, int R)
{
    int row = blockIdx.x;
    int tok = (row < U) ? a_idx[perm[R + row]] : b_idx[row - U];
    const float* s = src + (long)tok * CC;
    float* d = buf + (long)row * CC;
    for (int c = threadIdx.x; c < CC; c += 256) d[c] = s[c];
}
__global__ void __launch_bounds__(256) scatter_add_kernel(const float* __restrict__ src, float* __restrict__ buf,
    const int* __restrict__ a_idx, const int* __restrict__ perm, const int* __restrict__ dst, int U)
{
    int e = blockIdx.x;
    int tok = a_idx[perm[e]];
    float* d = buf + (long)(U + dst[e]) * CC;
    const float* s = src + (long)tok * CC;
    for (int c = threadIdx.x; c < CC; c += 256) atomicAdd(&d[c], s[c]);
}
__global__ void __launch_bounds__(256) div_cnt_kernel(float* __restrict__ buf, const int* __restrict__ cnt, int U) {
    int dr = blockIdx.x;
    float cf = (float)cnt[dr];
    float* p = buf + (long)(U + dr) * CC;
    for (int c = threadIdx.x; c < CC; c += 256) p[c] = p[c] / cf;
}

// ---------------- single-pass softmax -> bf16 hi/lo planes ----------------
__global__ void __launch_bounds__(256) softmax_b_kernel(const float* __restrict__ S,
    bf16* __restrict__ sh, bf16* __restrict__ sl)
{
    long row = blockIdx.x;
    const float4 v4 = ((const float4*)(S + row * MK))[threadIdx.x];
    float v[4] = {v4.x, v4.y, v4.z, v4.w};
    __shared__ float red[256];
    int tid = threadIdx.x;
    float m = fmaxf(fmaxf(v[0], v[1]), fmaxf(v[2], v[3]));
    red[tid] = m; __syncthreads();
    for (int off = 128; off; off >>= 1) { if (tid < off) red[tid] = fmaxf(red[tid], red[tid + off]); __syncthreads(); }
    float mx = red[0];
    __syncthreads();
    float e[4], s = 0.f;
#pragma unroll
    for (int i = 0; i < 4; i++) { e[i] = expf(v[i] - mx); s += e[i]; }
    red[tid] = s; __syncthreads();
    for (int off = 128; off; off >>= 1) { if (tid < off) red[tid] += red[tid + off]; __syncthreads(); }
    float inv = 1.0f / red[0];
    uint32_t hp[2], lp[2];
#pragma unroll
    for (int i = 0; i < 2; i++) {
        float a = e[2 * i] * inv, b = e[2 * i + 1] * inv;
        bf16 ha = __float2bfloat16(a), hb = __float2bfloat16(b);
        hp[i] = pkbf(ha, hb);
        lp[i] = pkbf(__float2bfloat16(a - __bfloat162float(ha)),
                     __float2bfloat16(b - __bfloat162float(hb)));
    }
    ((uint2*)(sh + row * MK))[tid] = make_uint2(hp[0], hp[1]);
    ((uint2*)(sl + row * MK))[tid] = make_uint2(lp[0], lp[1]);
}

// ---------------- unmerge ----------------
__global__ void __launch_bounds__(256) unmerge_kernel(const float* __restrict__ proj, float* __restrict__ out,
    const int* __restrict__ a_idx, const int* __restrict__ b_idx,
    const int* __restrict__ perm, const int* __restrict__ dst)
{
    int rid = blockIdx.x;
    int srcrow, tok;
    if (rid < NDQ) { srcrow = UQ + rid; tok = b_idx[rid]; }
    else if (rid < NDQ + UQ) { int u = rid - NDQ; srcrow = u; tok = a_idx[perm[RQ + u]]; }
    else { int e = rid - (NDQ + UQ); srcrow = UQ + dst[e]; tok = a_idx[perm[e]]; }
    const float* s = proj + (long)srcrow * CC;
    float* d = out + (long)tok * CC;
    for (int c = threadIdx.x; c < CC; c += 256) d[c] = s[c];
}

// ---------------- host launcher ----------------
#define SM_6_64  (3 * (3 * 16384 + 3 * 8192))
#define SM_3_128 (3 * (2 * 16384 + 2 * 16384))
#define SM_3_64  (3 * (2 * 16384 + 2 * 8192))
#define SM_1_128 (3 * (16384 + 16384))
#define SM_1_64  (3 * (16384 + 8192))

extern "C" void kernel_launch(void* const* d_in, const int* in_sizes, int n_in,
                              void* d_out, int out_size)
{
    (void)in_sizes; (void)n_in; (void)out_size;
    const float* x   = (const float*)d_in[0];
    const float* srw = (const float*)d_in[1];
    const float* srb = (const float*)d_in[2];
    const float* lng = (const float*)d_in[3];
    const float* lnb = (const float*)d_in[4];
    const float* Wq  = (const float*)d_in[5];
    const float* Wkv = (const float*)d_in[6];
    const float* Wp  = (const float*)d_in[7];
    const float* bp  = (const float*)d_in[8];
    float* out = (float*)d_out;

    cudaFuncSetAttribute(mmg<6, 64>,  cudaFuncAttributeMaxDynamicSharedMemorySize, SM_6_64);
    cudaFuncSetAttribute(mmg<3, 128>, cudaFuncAttributeMaxDynamicSharedMemorySize, SM_3_128);
    cudaFuncSetAttribute(mmg<3, 64>,  cudaFuncAttributeMaxDynamicSharedMemorySize, SM_3_64);
    cudaFuncSetAttribute(mmg<1, 128>, cudaFuncAttributeMaxDynamicSharedMemorySize, SM_1_128);
    cudaFuncSetAttribute(mmg<1, 64>,  cudaFuncAttributeMaxDynamicSharedMemorySize, SM_1_64);

    float *xk, *mnq, *mnk, *nvq, *nvk, *rmax, *xq, *xkm, *qm, *kvm, *S, *ao, *proj;
    u64 *keyq, *keyk;
    int *permq, *permk, *dstq, *dstk, *cntq, *cntk, *aq, *bq, *ak, *bk, *ctok;
    bf16 *x3, *bt3, *mq1, *mk1, *xq2, *xkm2, *wq2, *wkv2, *wp2, *qp2, *kp2, *vp2, *ao2, *sh, *sl;
    cudaGetSymbolAddress((void**)&xk, g_xk);
    cudaGetSymbolAddress((void**)&mnq, g_mnq);
    cudaGetSymbolAddress((void**)&mnk, g_mnk);
    cudaGetSymbolAddress((void**)&nvq, g_nvq);
    cudaGetSymbolAddress((void**)&nvk, g_nvk);
    cudaGetSymbolAddress((void**)&rmax, g_rmax);
    cudaGetSymbolAddress((void**)&xq, g_xq);
    cudaGetSymbolAddress((void**)&xkm, g_xkm);
    cudaGetSymbolAddress((void**)&qm, g_qm);
    cudaGetSymbolAddress((void**)&kvm, g_kvm);
    cudaGetSymbolAddress((void**)&S, g_S);
    cudaGetSymbolAddress((void**)&ao, g_ao);
    cudaGetSymbolAddress((void**)&proj, g_proj);
    cudaGetSymbolAddress((void**)&keyq, g_keyq);
    cudaGetSymbolAddress((void**)&keyk, g_keyk);
    cudaGetSymbolAddress((void**)&permq, g_permq);
    cudaGetSymbolAddress((void**)&permk, g_permk);
    cudaGetSymbolAddress((void**)&dstq, g_dstq);
    cudaGetSymbolAddress((void**)&dstk, g_dstk);
    cudaGetSymbolAddress((void**)&cntq, g_cntq);
    cudaGetSymbolAddress((void**)&cntk, g_cntk);
    cudaGetSymbolAddress((void**)&aq, g_aq);
    cudaGetSymbolAddress((void**)&bq, g_bq);
    cudaGetSymbolAddress((void**)&ak, g_ak);
    cudaGetSymbolAddress((void**)&bk, g_bk);
    cudaGetSymbolAddress((void**)&ctok, g_ctok);
    cudaGetSymbolAddress((void**)&x3, g_x3);
    cudaGetSymbolAddress((void**)&bt3, g_bt3);
    cudaGetSymbolAddress((void**)&mq1, g_mq1);
    cudaGetSymbolAddress((void**)&mk1, g_mk1);
    cudaGetSymbolAddress((void**)&xq2, g_xq2);
    cudaGetSymbolAddress((void**)&xkm2, g_xkm2);
    cudaGetSymbolAddress((void**)&wq2, g_wq2);
    cudaGetSymbolAddress((void**)&wkv2, g_wkv2);
    cudaGetSymbolAddress((void**)&wp2, g_wp2);
    cudaGetSymbolAddress((void**)&qp2, g_qp2);
    cudaGetSymbolAddress((void**)&kp2, g_kp2);
    cudaGetSymbolAddress((void**)&vp2, g_vp2);
    cudaGetSymbolAddress((void**)&ao2, g_ao2);
    cudaGetSymbolAddress((void**)&sh, g_sh);
    cudaGetSymbolAddress((void**)&sl, g_sl);

    const long PXQ = (long)NQ * CC;
    const long PBT = (long)8 * CC * CC;
    const long PQ2 = (long)MQ * CC;
    const long PK2 = (long)MK * CC;
    const long PWQ = (long)CC * CC;
    const long PWKV = (long)2 * CC * CC;
    const long PQP = (long)HEADS * MQ * 128;
    const long PKP = (long)HEADS * MK * 128;
    const long PVP = (long)HEADS * HD * MK;
    float* Skv = S + (long)NAQ * NDQ;

    // 1-3: conv prerequisites
    split3_kernel<<<(int)((PXQ + 255) / 256), 256>>>(x, x3, x3 + PXQ, x3 + 2 * PXQ, PXQ);
    split3_bt_kernel<<<(int)((PBT + 255) / 256), 256>>>(srw, bt3, bt3 + PBT, bt3 + 2 * PBT);
    conv_tok_kernel<<<(8 * N2 + 255) / 256, 256>>>(ctok);
    // 4: conv GEMM (profiled slot)
    mmg<6, 64><<<dim3(CC / 64, N2 / 128, 1), 512, SM_6_64>>>(
        x3, x3 + PXQ, x3 + 2 * PXQ, CC, 0,
        bt3, bt3 + PBT, bt3 + 2 * PBT, CC, 0, (long)CC * CC,
        xk, CC, 0, srb, 1.f, CC, CC, 8, ctok, N2, nullptr);
    // 5: fused LN + rownorm + cvt
    ln_norm_kernel<<<N2, 256>>>(xk, lng, lnb, mnk, mk1);
    build_idx_kernel<<<(NQ + 255) / 256, 256>>>(D0, H0, W0, aq, bq);
    build_idx_kernel<<<(N2 + 255) / 256, 256>>>(D0 / 2, H0 / 2, W0 / 2, ak, bk);

    // ---- q-side BSM ----
    rownorm_cvt_kernel<<<NQ, 256>>>(x, mnq, mq1);
    mmg<1, 128><<<dim3(NDQ / 128, NAQ / 128, 1), 512, SM_1_128>>>(
        mq1, nullptr, nullptr, CC, 0,
        mq1, nullptr, nullptr, CC, 0, 0,
        S, NDQ, 0, nullptr, 1.f, NDQ, CC, 1, aq, 0, bq);
    rowmax_kernel<<<NAQ / 8, 256>>>(S, rmax, NDQ);
    refine_kernel<<<NAQ / 8, 256>>>(S, NDQ, mnq, aq, bq, rmax, keyq, 2e-3f);
    unpack_val_kernel<<<(NAQ + 255) / 256, 256>>>(keyq, nvq, NAQ);
    rank_kernel<<<NAQ / 256, 256>>>(nvq, permq, NAQ);
    set_int_kernel<<<(NDQ + 255) / 256, 256>>>(cntq, NDQ, 1);
    fill_dst_kernel<<<(RQ + 255) / 256, 256>>>(permq, keyq, dstq, cntq, RQ);
    merge_gather_kernel<<<MQ, 256>>>(x, xq, aq, bq, permq, UQ, RQ);
    scatter_add_kernel<<<RQ, 256>>>(x, xq, aq, permq, dstq, UQ);
    div_cnt_kernel<<<NDQ, 256>>>(xq, cntq, UQ);

    // ---- kv-side BSM ----
    mmg<1, 64><<<dim3(NDK / 64, NAK / 128, 1), 512, SM_1_64>>>(
        mk1, nullptr, nullptr, CC, 0,
        mk1, nullptr, nullptr, CC, 0, 0,
        Skv, NDK, 0, nullptr, 1.f, NDK, CC, 1, ak, 0, bk);
    rowmax_kernel<<<NAK / 8, 256>>>(Skv, rmax, NDK);
    refine_kernel<<<NAK / 8, 256>>>(Skv, NDK, mnk, ak, bk, rmax, keyk, 2e-3f);
    unpack_val_kernel<<<(NAK + 255) / 256, 256>>>(keyk, nvk, NAK);
    rank_kernel<<<NAK / 256, 256>>>(nvk, permk, NAK);
    set_int_kernel<<<1, 256>>>(cntk, NDK, 1);
    fill_dst_kernel<<<(RK + 255) / 256, 256>>>(permk, keyk, dstk, cntk, RK);
    merge_gather_kernel<<<MK, 256>>>(xk, xkm, ak, bk, permk, UK, RK);
    scatter_add_kernel<<<RK, 256>>>(xk, xkm, ak, permk, dstk, UK);
    div_cnt_kernel<<<NDK, 256>>>(xkm, cntk, UK);

    // ---- projections (3-product) ----
    split2_kernel<<<(int)((PWQ + 255) / 256), 256>>>(Wq, wq2, wq2 + PWQ, PWQ);
    split2_kernel<<<(int)((PWKV + 255) / 256), 256>>>(Wkv, wkv2, wkv2 + PWKV, PWKV);
    split2_kernel<<<(int)((PWQ + 255) / 256), 256>>>(Wp, wp2, wp2 + PWQ, PWQ);
    split2_kernel<<<(int)((PQ2 + 255) / 256), 256>>>(xq, xq2, xq2 + PQ2, PQ2);
    split2_kernel<<<(int)((PK2 + 255) / 256), 256>>>(xkm, xkm2, xkm2 + PK2, PK2);
    mmg<3, 128><<<dim3(CC / 128, MQ / 128, 1), 512, SM_3_128>>>(
        xq2, xq2 + PQ2, nullptr, CC, 0,
        wq2, wq2 + PWQ, nullptr, CC, 0, 0,
        qm, CC, 0, nullptr, 1.f, CC, CC, 1, nullptr, 0, nullptr);
    mmg<3, 128><<<dim3(2 * CC / 128, MK / 128, 1), 512, SM_3_128>>>(
        xkm2, xkm2 + PK2, nullptr, CC, 0,
        wkv2, wkv2 + PWKV, nullptr, CC, 0, 0,
        kvm, 2 * CC, 0, nullptr, 1.f, 2 * CC, CC, 1, nullptr, 0, nullptr);

    // ---- head prep (padded K=128) ----
    split_qpad_kernel<<<(int)((PQP + 255) / 256), 256>>>(qm, qp2, qp2 + PQP);
    split_kpad_kernel<<<(int)((PKP + 255) / 256), 256>>>(kvm, kp2, kp2 + PKP);
    split_vT_kernel<<<(int)((PVP + 255) / 256), 256>>>(kvm, vp2, vp2 + PVP);

    // ---- attention ----
    float scl = 1.0f / sqrtf((float)HD);
    mmg<3, 128><<<dim3(MK / 128, MQ / 128, HEADS), 512, SM_3_128>>>(
        qp2, qp2 + PQP, nullptr, 128, (long)MQ * 128,
        kp2, kp2 + PKP, nullptr, 128, (long)MK * 128, 0,
        S, MK, (long)MQ * MK, nullptr, scl, MK, 128, 1, nullptr, 0, nullptr);
    softmax_b_kernel<<<HEADS * MQ, 256>>>(S, sh, sl);
    mmg<3, 64><<<dim3(2, MQ / 128, HEADS), 512, SM_3_64>>>(
        sh, sl, nullptr, MK, (long)MQ * MK,
        vp2, vp2 + PVP, nullptr, MK, (long)HD * MK, 0,
        ao, CC, HD, nullptr, 1.f, HD, MK, 1, nullptr, 0, nullptr);

    // ---- output projection + unmerge ----
    split2_kernel<<<(int)((PQ2 + 255) / 256), 256>>>(ao, ao2, ao2 + PQ2, PQ2);
    mmg<3, 128><<<dim3(CC / 128, MQ / 128, 1), 512, SM_3_128>>>(
        ao2, ao2 + PQ2, nullptr, CC, 0,
        wp2, wp2 + PWQ, nullptr, CC, 0, 0,
        proj, CC, 0, bp, 1.f, CC, CC, 1, nullptr, 0, nullptr);
    unmerge_kernel<<<NQ, 256>>>(proj, out, aq, bq, permq, dstq);
}

// round 9
// speedup vs baseline: 2.1322x; 1.0709x over previous
#include <cuda_runtime.h>
#include <cuda_bf16.h>
#include <math.h>
#include <stdint.h>

// ---------------- static problem sizes ----------------
#define CC    768
#define D0    16
#define H0    32
#define W0    32
#define NQ    16384
#define NDQ   2048
#define NAQ   14336
#define RQ    8192
#define UQ    6144
#define MQ    8192
#define N2    2048
#define NDK   256
#define NAK   1792
#define RK    1024
#define UK    768
#define MK    1024
#define HEADS 8
#define HD    96

typedef __nv_bfloat16 bf16;
typedef unsigned long long u64;

// ---------------- device scratch ----------------
__device__ float g_xk[N2 * CC];
__device__ float g_mnq[NQ * CC];
__device__ float g_mnk[N2 * CC];
__device__ u64   g_keyq[NAQ];
__device__ u64   g_keyk[NAK];
__device__ float g_nvq[NAQ];
__device__ float g_nvk[NAK];
__device__ float g_rmax[NAQ];
__device__ int g_permq[NAQ];
__device__ int g_permk[NAK];
__device__ int g_dstq[RQ];
__device__ int g_dstk[RK];
__device__ int g_cntq[NDQ];
__device__ int g_cntk[NDK];
__device__ int g_aq[NAQ];
__device__ int g_bq[NDQ];
__device__ int g_ak[NAK];
__device__ int g_bk[NDK];
__device__ int g_ctok[8 * N2];
__device__ float g_xq[MQ * CC];
__device__ float g_xkm[MK * CC];
__device__ float g_qm[MQ * CC];
__device__ float g_kvm[MK * 2 * CC];
__device__ float g_S[(long)HEADS * MQ * MK];
__device__ float g_ao[MQ * CC];
__device__ float g_proj[MQ * CC];

// bf16 planes
__device__ bf16 g_x3[3][NQ * CC];
__device__ bf16 g_bt3[3][8 * CC * CC];
__device__ bf16 g_mq1[NQ * CC];
__device__ bf16 g_mk1[N2 * CC];
__device__ bf16 g_xq2[2][MQ * CC];
__device__ bf16 g_xkm2[2][MK * CC];
__device__ bf16 g_wq2[2][CC * CC];
__device__ bf16 g_wkv2[2][2 * CC * CC];
__device__ bf16 g_wp2[2][CC * CC];
__device__ bf16 g_qp2[2][HEADS * MQ * 128];
__device__ bf16 g_kp2[2][HEADS * MK * 128];
__device__ bf16 g_vp2[2][HEADS * HD * MK];
__device__ bf16 g_ao2[2][MQ * CC];
__device__ bf16 g_sh[(long)HEADS * MQ * MK];
__device__ bf16 g_sl[(long)HEADS * MQ * MK];

__device__ __forceinline__ uint32_t smem_u32(const void* p) {
    uint32_t a;
    asm("{ .reg .u64 t; cvta.to.shared.u64 t, %1; cvt.u32.u64 %0, t; }" : "=r"(a) : "l"(p));
    return a;
}
__device__ __forceinline__ uint32_t pkbf(bf16 a, bf16 b) {
    return (uint32_t)__bfloat16_as_ushort(a) | ((uint32_t)__bfloat16_as_ushort(b) << 16);
}
#define SWZ(o) ((o) ^ (((o) >> 3) & 0x70))
#define MMA16816(d, a, b0v, b1v) \
    asm volatile("mma.sync.aligned.m16n8k16.row.col.f32.bf16.bf16.f32 " \
        "{%0,%1,%2,%3}, {%4,%5,%6,%7}, {%8,%9}, {%0,%1,%2,%3};" \
        : "+f"((d)[0]), "+f"((d)[1]), "+f"((d)[2]), "+f"((d)[3]) \
        : "r"((a)[0]), "r"((a)[1]), "r"((a)[2]), "r"((a)[3]), "r"(b0v), "r"(b1v))
#define LDSM4(r, a) \
    asm volatile("ldmatrix.sync.aligned.m8n8.x4.shared.b16 {%0,%1,%2,%3}, [%4];" \
        : "=r"((r)[0]), "=r"((r)[1]), "=r"((r)[2]), "=r"((r)[3]) : "r"(a))
#define CPA(dst, src, sz) \
    asm volatile("cp.async.cg.shared.global [%0], [%1], 16, %2;" :: "r"(dst), "l"(src), "r"(sz) : "memory")
#define CPCOMMIT() asm volatile("cp.async.commit_group;" ::: "memory")
#define CPWAIT1()  asm volatile("cp.async.wait_group 1;" ::: "memory")

// ---------------- pipelined ldmatrix mma.sync split-bf16 GEMM ----------------
// C[M,N] = scale * A[M,K] @ B[N,K]^T (+bias), over ntap segments.
// Block 64 x TN, k-tile 64, STAGES-deep cp.async pipeline, 16 warps (4m x 4n),
// warp tile 16 x (TN/4). Sized for 2 CTAs/SM (<=64 regs, <=96KB smem).
template <int NPR, int TN, int STAGES>
__global__ void __launch_bounds__(512, 2) mmg(
    const bf16* A0, const bf16* A1, const bf16* A2, long lda, long ahs,
    const bf16* B0, const bf16* B1, const bf16* B2, long ldb, long bhs, long bseg,
    float* C, long ldc, long chs, const float* bias, float scale,
    int N, int K, int ntap, const int* gA, int gAs, const int* gB)
{
    constexpr int nA = (NPR == 6) ? 3 : (NPR == 3) ? 2 : 1;
    constexpr int nB = nA;
    constexpr int PLA = 8192;          // 64 rows x 128 B
    constexpr int PLB = TN * 128;
    constexpr int STG = nA * PLA + nB * PLB;
    constexpr int NJ = TN / 32;        // n-tiles of 8 per warp
    extern __shared__ char sm[];
    const uint32_t su = smem_u32(sm);

    const int tid = threadIdx.x, lane = tid & 31, wid = tid >> 5;
    const int wm = wid >> 2, wn = wid & 3;
    const int m0 = blockIdx.y * 64, n0 = blockIdx.x * TN, z = blockIdx.z;
    const int lq = lane >> 2, lr = lane & 3;

    // loaders (512 threads)
    const int lrA = tid >> 3, secA = tid & 7;                 // 64 rows x 8x16B
    const int lrB = (TN == 128) ? (tid >> 2) : (tid >> 3);
    const int secB = (TN == 128) ? (tid & 3) : (tid & 7);
    const int nrow = n0 + lrB;
    const bool bval = nrow < N;
    const long brow = bval ? (gB ? (long)gB[nrow] : (long)nrow) : 0;
    const uint32_t bsz = bval ? 16u : 0u;

    const uint32_t dA0 = SWZ((uint32_t)(lrA * 128 + secA * 16));
    const uint32_t dB0 = (TN == 128) ? SWZ((uint32_t)(lrB * 128 + secB * 32))
                                     : SWZ((uint32_t)(lrB * 128 + secB * 16));
    const uint32_t dB1 = (TN == 128) ? SWZ((uint32_t)(lrB * 128 + secB * 32 + 16)) : 0u;

    const int kc = K >> 6;
    const int nch = ntap * kc;
    const bf16* Ap[3] = {A0, A1, A2};
    const bf16* Bp[3] = {B0, B1, B2};

    float acc[NJ][4];
#pragma unroll
    for (int j = 0; j < NJ; j++)
#pragma unroll
        for (int t = 0; t < 4; t++) acc[j][t] = 0.f;

    auto issue = [&](int c) {
        const int stg = c % STAGES;
        const uint32_t sb = su + stg * STG;
        const int tap = c / kc;
        const int k0 = (c - tap * kc) << 6;
        const long arow = gA ? (long)gA[tap * gAs + m0 + lrA] : (long)(m0 + lrA);
#pragma unroll
        for (int p = 0; p < nA; p++) {
            const bf16* s0 = Ap[p] + (long)z * ahs + arow * lda + k0 + secA * 8;
            CPA(sb + p * PLA + dA0, s0, 16u);
        }
#pragma unroll
        for (int p = 0; p < nB; p++) {
            const bf16* s0 = Bp[p] + (long)z * bhs + (long)tap * bseg + brow * ldb + k0
                           + secB * (TN == 128 ? 16 : 8);
            CPA(sb + nA * PLA + p * PLB + dB0, s0, bsz);
            if (TN == 128) CPA(sb + nA * PLA + p * PLB + dB1, s0 + 8, bsz);
        }
        CPCOMMIT();
    };

    auto compute = [&](int stg) {
        const uint32_t sb = su + stg * STG;
        const int pa6[6] = {0, 0, 1, 1, 0, 2}, pb6[6] = {0, 1, 0, 1, 2, 0};
#pragma unroll
        for (int ks = 0; ks < 4; ks++) {
            uint32_t af[nA][4];
#pragma unroll
            for (int p = 0; p < nA; p++) {
                uint32_t off = (uint32_t)((wm * 16 + (lane & 15)) * 128
                                          + ks * 32 + ((lane >> 4) << 4));
                LDSM4(af[p], sb + p * PLA + SWZ(off));
            }
            uint32_t bl[nB][NJ], bh[nB][NJ];
            if constexpr (TN == 128) {
#pragma unroll
                for (int p = 0; p < nB; p++) {
                    uint32_t r0[4], r1[4];
                    uint32_t off0 = (uint32_t)((wn * 32 + (lane >> 3) * 8 + (lane & 7)) * 128 + ks * 32);
                    LDSM4(r0, sb + nA * PLA + p * PLB + SWZ(off0));
                    LDSM4(r1, sb + nA * PLA + p * PLB + SWZ(off0 + 16));
#pragma unroll
                    for (int j = 0; j < 4; j++) { bl[p][j] = r0[j]; bh[p][j] = r1[j]; }
                }
            } else {
#pragma unroll
                for (int p = 0; p < nB; p++) {
                    uint32_t r[4];
                    const int tileB = (lane >> 3) & 1, khB = lane >> 4;
                    uint32_t off = (uint32_t)((wn * 16 + tileB * 8 + (lane & 7)) * 128
                                              + ks * 32 + khB * 16);
                    LDSM4(r, sb + nA * PLA + p * PLB + SWZ(off));
                    bl[p][0] = r[0]; bl[p][1] = r[1]; bh[p][0] = r[2]; bh[p][1] = r[3];
                }
            }
#pragma unroll
            for (int pr = 0; pr < NPR; pr++) {
                const int pA = (NPR == 1) ? 0 : pa6[pr];
                const int pB = (NPR == 1) ? 0 : pb6[pr];
#pragma unroll
                for (int j = 0; j < NJ; j++)
                    MMA16816(acc[j], af[pA], bl[pB][j], bh[pB][j]);
            }
        }
    };

    issue(0);
    for (int c = 0; c < nch; c++) {
        if (c + 1 < nch) issue(c + 1);
        else CPCOMMIT();       // one commit per iteration -> wait_group 1 exact
        CPWAIT1();
        __syncthreads();
        compute(c % STAGES);
        if (STAGES == 2) __syncthreads();   // protect stage reuse (2-stage)
    }

    // ---- epilogue ----
    const int r = m0 + wm * 16 + lq;
#pragma unroll
    for (int j = 0; j < NJ; j++) {
        const int cb = n0 + wn * (TN / 4) + j * 8 + lr * 2;
        if (cb < N) {
            float bb0 = bias ? bias[cb] : 0.f;
            float bb1 = bias ? bias[cb + 1] : 0.f;
            float* p0 = C + (long)z * chs + (long)r * ldc + cb;
            float* p1 = C + (long)z * chs + (long)(r + 8) * ldc + cb;
            p0[0] = acc[j][0] * scale + bb0;
            p0[1] = acc[j][1] * scale + bb1;
            p1[0] = acc[j][2] * scale + bb0;
            p1[1] = acc[j][3] * scale + bb1;
        }
    }
}

// ---------------- utility / prep kernels ----------------
__global__ void set_int_kernel(int* p, int n, int v) {
    int i = blockIdx.x * 256 + threadIdx.x;
    if (i < n) p[i] = v;
}
__global__ void build_idx_kernel(int D, int H, int W, int* a_idx, int* b_idx) {
    int n = D * H * W;
    int t = blockIdx.x * 256 + threadIdx.x;
    if (t >= n) return;
    int z = t / (H * W), y = (t / W) % H, xx = t % W;
    int hw2 = (H >> 1) * (W >> 1);
    if (((z | y | xx) & 1) == 0) {
        b_idx[(z >> 1) * hw2 + (y >> 1) * (W >> 1) + (xx >> 1)] = t;
    } else {
        int cez = (z + 1) >> 1, cey = (y + 1) >> 1, cex = (xx + 1) >> 1;
        int before = cez * hw2;
        if ((z & 1) == 0) { before += cey * (W >> 1); if ((y & 1) == 0) before += cex; }
        a_idx[t - before] = t;
    }
}
__global__ void conv_tok_kernel(int* t) {
    int i = blockIdx.x * 256 + threadIdx.x;
    if (i >= 8 * N2) return;
    int tap = i >> 11, m = i & 2047;
    int kz = tap >> 2, ky = (tap >> 1) & 1, kx = tap & 1;
    int z2 = m >> 8, y2 = (m >> 4) & 15, x2 = m & 15;
    t[i] = (2 * z2 + kz) * (H0 * W0) + (2 * y2 + ky) * W0 + (2 * x2 + kx);
}
__global__ void split3_kernel(const float* __restrict__ s, bf16* p0, bf16* p1, bf16* p2, long n) {
    long i = (long)blockIdx.x * 256 + threadIdx.x;
    if (i >= n) return;
    float v = s[i];
    bf16 h = __float2bfloat16(v); float r = v - __bfloat162float(h);
    bf16 m = __float2bfloat16(r); float r2 = r - __bfloat162float(m);
    p0[i] = h; p1[i] = m; p2[i] = __float2bfloat16(r2);
}
__global__ void split2_kernel(const float* __restrict__ s, bf16* p0, bf16* p1, long n) {
    long i = (long)blockIdx.x * 256 + threadIdx.x;
    if (i >= n) return;
    float v = s[i];
    bf16 h = __float2bfloat16(v);
    p0[i] = h; p1[i] = __float2bfloat16(v - __bfloat162float(h));
}
__global__ void split3_bt_kernel(const float* __restrict__ w, bf16* p0, bf16* p1, bf16* p2) {
    long i = (long)blockIdx.x * 256 + threadIdx.x;
    if (i >= (long)8 * CC * CC) return;
    int tap = (int)(i / (CC * CC));
    int rem = (int)(i - (long)tap * CC * CC);
    int n = rem / CC, k = rem - n * CC;
    float v = w[(long)n * (CC * 8) + k * 8 + tap];
    bf16 h = __float2bfloat16(v); float r = v - __bfloat162float(h);
    bf16 m = __float2bfloat16(r);
    p0[i] = h; p1[i] = m; p2[i] = __float2bfloat16(r - __bfloat162float(m));
}
__global__ void split_qpad_kernel(const float* __restrict__ qm, bf16* p0, bf16* p1) {
    long i = (long)blockIdx.x * 256 + threadIdx.x;
    if (i >= (long)HEADS * MQ * 128) return;
    int h = (int)(i >> 20);
    int m = (int)((i >> 7) & (MQ - 1));
    int k = (int)(i & 127);
    float v = (k < HD) ? qm[(long)m * CC + h * HD + k] : 0.f;
    bf16 hi = __float2bfloat16(v);
    p0[i] = hi; p1[i] = __float2bfloat16(v - __bfloat162float(hi));
}
__global__ void split_kpad_kernel(const float* __restrict__ kvm, bf16* p0, bf16* p1) {
    long i = (long)blockIdx.x * 256 + threadIdx.x;
    if (i >= (long)HEADS * MK * 128) return;
    int h = (int)(i >> 17);
    int m = (int)((i >> 7) & (MK - 1));
    int k = (int)(i & 127);
    float v = (k < HD) ? kvm[(long)m * (2 * CC) + h * HD + k] : 0.f;
    bf16 hi = __float2bfloat16(v);
    p0[i] = hi; p1[i] = __float2bfloat16(v - __bfloat162float(hi));
}
__global__ void split_vT_kernel(const float* __restrict__ kvm, bf16* p0, bf16* p1) {
    long i = (long)blockIdx.x * 256 + threadIdx.x;
    if (i >= (long)HEADS * HD * MK) return;
    int h = (int)(i / (HD * MK));
    int rem = (int)(i - (long)h * HD * MK);
    int n = rem >> 10, k = rem & (MK - 1);
    float v = kvm[(long)k * (2 * CC) + CC + h * HD + n];
    bf16 hi = __float2bfloat16(v);
    p0[i] = hi; p1[i] = __float2bfloat16(v - __bfloat162float(hi));
}

// ---------------- fused LN -> xk, mnk, mk1 ----------------
__global__ void __launch_bounds__(256) ln_norm_kernel(float* __restrict__ xk,
    const float* __restrict__ g, const float* __restrict__ b,
    float* __restrict__ mnk, bf16* __restrict__ mk1)
{
    int row = blockIdx.x;
    float* p = xk + (long)row * CC;
    __shared__ float red[256];
    int tid = threadIdx.x;
    float v0 = p[tid], v1 = p[tid + 256], v2 = p[tid + 512];
    red[tid] = v0 + v1 + v2; __syncthreads();
    for (int off = 128; off; off >>= 1) { if (tid < off) red[tid] += red[tid + off]; __syncthreads(); }
    float mean = red[0] / (float)CC;
    __syncthreads();
    float d0 = v0 - mean, d1 = v1 - mean, d2 = v2 - mean;
    red[tid] = d0 * d0 + d1 * d1 + d2 * d2; __syncthreads();
    for (int off = 128; off; off >>= 1) { if (tid < off) red[tid] += red[tid + off]; __syncthreads(); }
    float var = red[0] / (float)CC;
    float inv = (float)(1.0 / sqrt((double)var + 1e-5));
    __syncthreads();
    float y0 = d0 * inv * g[tid] + b[tid];
    float y1 = d1 * inv * g[tid + 256] + b[tid + 256];
    float y2 = d2 * inv * g[tid + 512] + b[tid + 512];
    p[tid] = y0; p[tid + 256] = y1; p[tid + 512] = y2;
    red[tid] = y0 * y0 + y1 * y1 + y2 * y2; __syncthreads();
    for (int off = 128; off; off >>= 1) { if (tid < off) red[tid] += red[tid + off]; __syncthreads(); }
    float nrm = (float)(1.0 / sqrt((double)red[0]));
    float* q = mnk + (long)row * CC;
    bf16* q1 = mk1 + (long)row * CC;
    float n0 = y0 * nrm, n1 = y1 * nrm, n2 = y2 * nrm;
    q[tid] = n0; q[tid + 256] = n1; q[tid + 512] = n2;
    q1[tid] = __float2bfloat16(n0); q1[tid + 256] = __float2bfloat16(n1); q1[tid + 512] = __float2bfloat16(n2);
}
__global__ void __launch_bounds__(256) rownorm_cvt_kernel(const float* __restrict__ src,
    float* __restrict__ dst, bf16* __restrict__ dst1)
{
    int row = blockIdx.x;
    const float* p = src + (long)row * CC;
    __shared__ float red[256];
    int tid = threadIdx.x;
    float v0 = p[tid], v1 = p[tid + 256], v2 = p[tid + 512];
    red[tid] = v0 * v0 + v1 * v1 + v2 * v2; __syncthreads();
    for (int off = 128; off; off >>= 1) { if (tid < off) red[tid] += red[tid + off]; __syncthreads(); }
    float inv = (float)(1.0 / sqrt((double)red[0]));
    float* q = dst + (long)row * CC;
    bf16* q1 = dst1 + (long)row * CC;
    float n0 = v0 * inv, n1 = v1 * inv, n2 = v2 * inv;
    q[tid] = n0; q[tid + 256] = n1; q[tid + 512] = n2;
    q1[tid] = __float2bfloat16(n0); q1[tid + 256] = __float2bfloat16(n1); q1[tid + 512] = __float2bfloat16(n2);
}

// ---------------- two-phase BSM scoring ----------------
__global__ void __launch_bounds__(256) rowmax_kernel(const float* __restrict__ S, float* __restrict__ rmax, int ncol) {
    int row = blockIdx.x * 8 + (threadIdx.x >> 5);
    int lane = threadIdx.x & 31;
    const float* p = S + (long)row * ncol;
    float m = -3.4e38f;
    for (int c = lane; c < ncol; c += 32) m = fmaxf(m, p[c]);
    for (int off = 16; off; off >>= 1) m = fmaxf(m, __shfl_xor_sync(0xffffffffu, m, off));
    if (lane == 0) rmax[row] = m;
}
__global__ void __launch_bounds__(256) refine_kernel(
    const float* __restrict__ S, int ncol, const float* __restrict__ mn,
    const int* __restrict__ a_idx, const int* __restrict__ b_idx,
    const float* __restrict__ rmax, u64* __restrict__ key, float margin)
{
    int row = blockIdx.x * 8 + (threadIdx.x >> 5);
    int lane = threadIdx.x & 31;
    const float* p = S + (long)row * ncol;
    float thr = rmax[row] - margin;
    const float* av = mn + (long)a_idx[row] * CC;
    float bestv = -3.4e38f;
    int bestd = 0;
    for (int base = 0; base < ncol; base += 32) {
        float s = p[base + lane];
        unsigned m = __ballot_sync(0xffffffffu, s >= thr);
        while (m) {
            int b = __ffs(m) - 1;
            m &= m - 1;
            int dst = base + b;
            const float* bv = mn + (long)b_idx[dst] * CC;
            float part = 0.f;
            for (int c = lane; c < CC; c += 32) part += av[c] * bv[c];
            for (int off = 16; off; off >>= 1) part += __shfl_xor_sync(0xffffffffu, part, off);
            if (part > bestv) { bestv = part; bestd = dst; }
        }
    }
    if (lane == 0) {
        unsigned u = __float_as_uint(bestv);
        unsigned o = (u & 0x80000000u) ? ~u : (u | 0x80000000u);
        key[row] = ((u64)o << 32) | (unsigned)(~bestd);
    }
}

// ---------------- BSM index machinery ----------------
__global__ void unpack_val_kernel(const u64* __restrict__ key, float* __restrict__ val, int n) {
    int i = blockIdx.x * 256 + threadIdx.x;
    if (i >= n) return;
    uint32_t o = (uint32_t)(key[i] >> 32);
    uint32_t u = (o & 0x80000000u) ? (o ^ 0x80000000u) : ~o;
    val[i] = __uint_as_float(u);
}
__global__ void __launch_bounds__(256) rank_kernel(const float* __restrict__ v, int* __restrict__ perm, int n) {
    int i = blockIdx.x * 256 + threadIdx.x;
    float vi = (i < n) ? v[i] : 0.f;
    int r = 0;
    __shared__ float sv[256];
    for (int base = 0; base < n; base += 256) {
        int j = base + threadIdx.x;
        sv[threadIdx.x] = (j < n) ? v[j] : -3.4e38f;
        __syncthreads();
        int lim = min(256, n - base);
        for (int t = 0; t < lim; t++) {
            float vj = sv[t];
            int j2 = base + t;
            if (vj > vi || (vj == vi && j2 < i)) r++;
        }
        __syncthreads();
    }
    if (i < n) perm[r] = i;
}
__global__ void fill_dst_kernel(const int* __restrict__ perm, const u64* __restrict__ key,
                                int* __restrict__ dst, int* __restrict__ cnt, int R) {
    int e = blockIdx.x * 256 + threadIdx.x;
    if (e >= R) return;
    int s = perm[e];
    uint32_t low = (uint32_t)(key[s]);
    int dd = (int)(~low);
    dst[e] = dd;
    atomicAdd(&cnt[dd], 1);
}
__global__ void __launch_bounds__(256) merge_gather_kernel(const float* __restrict__ src, float* __restrict__ buf,
    const int* __restrict__ a_idx, const int* __restrict__ b_idx,
    const int* __restrict__ perm, int U, int R)
{
    int row = blockIdx.x;
    int tok = (row < U) ? a_idx[perm[R + row]] : b_idx[row - U];
    const float* s = src + (long)tok * CC;
    float* d = buf + (long)row * CC;
    for (int c = threadIdx.x; c < CC; c += 256) d[c] = s[c];
}
__global__ void __launch_bounds__(256) scatter_add_kernel(const float* __restrict__ src, float* __restrict__ buf,
    const int* __restrict__ a_idx, const int* __restrict__ perm, const int* __restrict__ dst, int U)
{
    int e = blockIdx.x;
    int tok = a_idx[perm[e]];
    float* d = buf + (long)(U + dst[e]) * CC;
    const float* s = src + (long)tok * CC;
    for (int c = threadIdx.x; c < CC; c += 256) atomicAdd(&d[c], s[c]);
}
__global__ void __launch_bounds__(256) div_cnt_kernel(float* __restrict__ buf, const int* __restrict__ cnt, int U) {
    int dr = blockIdx.x;
    float cf = (float)cnt[dr];
    float* p = buf + (long)(U + dr) * CC;
    for (int c = threadIdx.x; c < CC; c += 256) p[c] = p[c] / cf;
}

// ---------------- single-pass softmax -> bf16 hi/lo planes ----------------
__global__ void __launch_bounds__(256) softmax_b_kernel(const float* __restrict__ S,
    bf16* __restrict__ sh, bf16* __restrict__ sl)
{
    long row = blockIdx.x;
    const float4 v4 = ((const float4*)(S + row * MK))[threadIdx.x];
    float v[4] = {v4.x, v4.y, v4.z, v4.w};
    __shared__ float red[256];
    int tid = threadIdx.x;
    float m = fmaxf(fmaxf(v[0], v[1]), fmaxf(v[2], v[3]));
    red[tid] = m; __syncthreads();
    for (int off = 128; off; off >>= 1) { if (tid < off) red[tid] = fmaxf(red[tid], red[tid + off]); __syncthreads(); }
    float mx = red[0];
    __syncthreads();
    float e[4], s = 0.f;
#pragma unroll
    for (int i = 0; i < 4; i++) { e[i] = expf(v[i] - mx); s += e[i]; }
    red[tid] = s; __syncthreads();
    for (int off = 128; off; off >>= 1) { if (tid < off) red[tid] += red[tid + off]; __syncthreads(); }
    float inv = 1.0f / red[0];
    uint32_t hp[2], lp[2];
#pragma unroll
    for (int i = 0; i < 2; i++) {
        float a = e[2 * i] * inv, b = e[2 * i + 1] * inv;
        bf16 ha = __float2bfloat16(a), hb = __float2bfloat16(b);
        hp[i] = pkbf(ha, hb);
        lp[i] = pkbf(__float2bfloat16(a - __bfloat162float(ha)),
                     __float2bfloat16(b - __bfloat162float(hb)));
    }
    ((uint2*)(sh + row * MK))[tid] = make_uint2(hp[0], hp[1]);
    ((uint2*)(sl + row * MK))[tid] = make_uint2(lp[0], lp[1]);
}

// ---------------- unmerge ----------------
__global__ void __launch_bounds__(256) unmerge_kernel(const float* __restrict__ proj, float* __restrict__ out,
    const int* __restrict__ a_idx, const int* __restrict__ b_idx,
    const int* __restrict__ perm, const int* __restrict__ dst)
{
    int rid = blockIdx.x;
    int srcrow, tok;
    if (rid < NDQ) { srcrow = UQ + rid; tok = b_idx[rid]; }
    else if (rid < NDQ + UQ) { int u = rid - NDQ; srcrow = u; tok = a_idx[perm[RQ + u]]; }
    else { int e = rid - (NDQ + UQ); srcrow = UQ + dst[e]; tok = a_idx[perm[e]]; }
    const float* s = proj + (long)srcrow * CC;
    float* d = out + (long)tok * CC;
    for (int c = threadIdx.x; c < CC; c += 256) d[c] = s[c];
}

// ---------------- host launcher ----------------
#define SM_6_64_2  (2 * (3 * 8192 + 3 * 8192))   // 96 KB
#define SM_3_64_3  (3 * (2 * 8192 + 2 * 8192))   // 96 KB
#define SM_1_128_3 (3 * (8192 + 16384))          // 72 KB
#define SM_1_64_3  (3 * (8192 + 8192))           // 48 KB

extern "C" void kernel_launch(void* const* d_in, const int* in_sizes, int n_in,
                              void* d_out, int out_size)
{
    (void)in_sizes; (void)n_in; (void)out_size;
    const float* x   = (const float*)d_in[0];
    const float* srw = (const float*)d_in[1];
    const float* srb = (const float*)d_in[2];
    const float* lng = (const float*)d_in[3];
    const float* lnb = (const float*)d_in[4];
    const float* Wq  = (const float*)d_in[5];
    const float* Wkv = (const float*)d_in[6];
    const float* Wp  = (const float*)d_in[7];
    const float* bp  = (const float*)d_in[8];
    float* out = (float*)d_out;

    cudaFuncSetAttribute(mmg<6, 64, 2>,  cudaFuncAttributeMaxDynamicSharedMemorySize, SM_6_64_2);
    cudaFuncSetAttribute(mmg<3, 64, 3>,  cudaFuncAttributeMaxDynamicSharedMemorySize, SM_3_64_3);
    cudaFuncSetAttribute(mmg<1, 128, 3>, cudaFuncAttributeMaxDynamicSharedMemorySize, SM_1_128_3);
    cudaFuncSetAttribute(mmg<1, 64, 3>,  cudaFuncAttributeMaxDynamicSharedMemorySize, SM_1_64_3);

    float *xk, *mnq, *mnk, *nvq, *nvk, *rmax, *xq, *xkm, *qm, *kvm, *S, *ao, *proj;
    u64 *keyq, *keyk;
    int *permq, *permk, *dstq, *dstk, *cntq, *cntk, *aq, *bq, *ak, *bk, *ctok;
    bf16 *x3, *bt3, *mq1, *mk1, *xq2, *xkm2, *wq2, *wkv2, *wp2, *qp2, *kp2, *vp2, *ao2, *sh, *sl;
    cudaGetSymbolAddress((void**)&xk, g_xk);
    cudaGetSymbolAddress((void**)&mnq, g_mnq);
    cudaGetSymbolAddress((void**)&mnk, g_mnk);
    cudaGetSymbolAddress((void**)&nvq, g_nvq);
    cudaGetSymbolAddress((void**)&nvk, g_nvk);
    cudaGetSymbolAddress((void**)&rmax, g_rmax);
    cudaGetSymbolAddress((void**)&xq, g_xq);
    cudaGetSymbolAddress((void**)&xkm, g_xkm);
    cudaGetSymbolAddress((void**)&qm, g_qm);
    cudaGetSymbolAddress((void**)&kvm, g_kvm);
    cudaGetSymbolAddress((void**)&S, g_S);
    cudaGetSymbolAddress((void**)&ao, g_ao);
    cudaGetSymbolAddress((void**)&proj, g_proj);
    cudaGetSymbolAddress((void**)&keyq, g_keyq);
    cudaGetSymbolAddress((void**)&keyk, g_keyk);
    cudaGetSymbolAddress((void**)&permq, g_permq);
    cudaGetSymbolAddress((void**)&permk, g_permk);
    cudaGetSymbolAddress((void**)&dstq, g_dstq);
    cudaGetSymbolAddress((void**)&dstk, g_dstk);
    cudaGetSymbolAddress((void**)&cntq, g_cntq);
    cudaGetSymbolAddress((void**)&cntk, g_cntk);
    cudaGetSymbolAddress((void**)&aq, g_aq);
    cudaGetSymbolAddress((void**)&bq, g_bq);
    cudaGetSymbolAddress((void**)&ak, g_ak);
    cudaGetSymbolAddress((void**)&bk, g_bk);
    cudaGetSymbolAddress((void**)&ctok, g_ctok);
    cudaGetSymbolAddress((void**)&x3, g_x3);
    cudaGetSymbolAddress((void**)&bt3, g_bt3);
    cudaGetSymbolAddress((void**)&mq1, g_mq1);
    cudaGetSymbolAddress((void**)&mk1, g_mk1);
    cudaGetSymbolAddress((void**)&xq2, g_xq2);
    cudaGetSymbolAddress((void**)&xkm2, g_xkm2);
    cudaGetSymbolAddress((void**)&wq2, g_wq2);
    cudaGetSymbolAddress((void**)&wkv2, g_wkv2);
    cudaGetSymbolAddress((void**)&wp2, g_wp2);
    cudaGetSymbolAddress((void**)&qp2, g_qp2);
    cudaGetSymbolAddress((void**)&kp2, g_kp2);
    cudaGetSymbolAddress((void**)&vp2, g_vp2);
    cudaGetSymbolAddress((void**)&ao2, g_ao2);
    cudaGetSymbolAddress((void**)&sh, g_sh);
    cudaGetSymbolAddress((void**)&sl, g_sl);

    const long PXQ = (long)NQ * CC;
    const long PBT = (long)8 * CC * CC;
    const long PQ2 = (long)MQ * CC;
    const long PK2 = (long)MK * CC;
    const long PWQ = (long)CC * CC;
    const long PWKV = (long)2 * CC * CC;
    const long PQP = (long)HEADS * MQ * 128;
    const long PKP = (long)HEADS * MK * 128;
    const long PVP = (long)HEADS * HD * MK;
    float* Skv = S + (long)NAQ * NDQ;

    // 1-3: conv prerequisites
    split3_kernel<<<(int)((PXQ + 255) / 256), 256>>>(x, x3, x3 + PXQ, x3 + 2 * PXQ, PXQ);
    split3_bt_kernel<<<(int)((PBT + 255) / 256), 256>>>(srw, bt3, bt3 + PBT, bt3 + 2 * PBT);
    conv_tok_kernel<<<(8 * N2 + 255) / 256, 256>>>(ctok);
    // 4: conv GEMM (profiled slot)
    mmg<6, 64, 2><<<dim3(CC / 64, N2 / 64, 1), 512, SM_6_64_2>>>(
        x3, x3 + PXQ, x3 + 2 * PXQ, CC, 0,
        bt3, bt3 + PBT, bt3 + 2 * PBT, CC, 0, (long)CC * CC,
        xk, CC, 0, srb, 1.f, CC, CC, 8, ctok, N2, nullptr);
    // 5: fused LN + rownorm + cvt
    ln_norm_kernel<<<N2, 256>>>(xk, lng, lnb, mnk, mk1);
    build_idx_kernel<<<(NQ + 255) / 256, 256>>>(D0, H0, W0, aq, bq);
    build_idx_kernel<<<(N2 + 255) / 256, 256>>>(D0 / 2, H0 / 2, W0 / 2, ak, bk);

    // ---- q-side BSM ----
    rownorm_cvt_kernel<<<NQ, 256>>>(x, mnq, mq1);
    mmg<1, 128, 3><<<dim3(NDQ / 128, NAQ / 64, 1), 512, SM_1_128_3>>>(
        mq1, nullptr, nullptr, CC, 0,
        mq1, nullptr, nullptr, CC, 0, 0,
        S, NDQ, 0, nullptr, 1.f, NDQ, CC, 1, aq, 0, bq);
    rowmax_kernel<<<NAQ / 8, 256>>>(S, rmax, NDQ);
    refine_kernel<<<NAQ / 8, 256>>>(S, NDQ, mnq, aq, bq, rmax, keyq, 2e-3f);
    unpack_val_kernel<<<(NAQ + 255) / 256, 256>>>(keyq, nvq, NAQ);
    rank_kernel<<<NAQ / 256, 256>>>(nvq, permq, NAQ);
    set_int_kernel<<<(NDQ + 255) / 256, 256>>>(cntq, NDQ, 1);
    fill_dst_kernel<<<(RQ + 255) / 256, 256>>>(permq, keyq, dstq, cntq, RQ);
    merge_gather_kernel<<<MQ, 256>>>(x, xq, aq, bq, permq, UQ, RQ);
    scatter_add_kernel<<<RQ, 256>>>(x, xq, aq, permq, dstq, UQ);
    div_cnt_kernel<<<NDQ, 256>>>(xq, cntq, UQ);

    // ---- kv-side BSM ----
    mmg<1, 64, 3><<<dim3(NDK / 64, NAK / 64, 1), 512, SM_1_64_3>>>(
        mk1, nullptr, nullptr, CC, 0,
        mk1, nullptr, nullptr, CC, 0, 0,
        Skv, NDK, 0, nullptr, 1.f, NDK, CC, 1, ak, 0, bk);
    rowmax_kernel<<<NAK / 8, 256>>>(Skv, rmax, NDK);
    refine_kernel<<<NAK / 8, 256>>>(Skv, NDK, mnk, ak, bk, rmax, keyk, 2e-3f);
    unpack_val_kernel<<<(NAK + 255) / 256, 256>>>(keyk, nvk, NAK);
    rank_kernel<<<NAK / 256, 256>>>(nvk, permk, NAK);
    set_int_kernel<<<1, 256>>>(cntk, NDK, 1);
    fill_dst_kernel<<<(RK + 255) / 256, 256>>>(permk, keyk, dstk, cntk, RK);
    merge_gather_kernel<<<MK, 256>>>(xk, xkm, ak, bk, permk, UK, RK);
    scatter_add_kernel<<<RK, 256>>>(xk, xkm, ak, permk, dstk, UK);
    div_cnt_kernel<<<NDK, 256>>>(xkm, cntk, UK);

    // ---- projections (3-product) ----
    split2_kernel<<<(int)((PWQ + 255) / 256), 256>>>(Wq, wq2, wq2 + PWQ, PWQ);
    split2_kernel<<<(int)((PWKV + 255) / 256), 256>>>(Wkv, wkv2, wkv2 + PWKV, PWKV);
    split2_kernel<<<(int)((PWQ + 255) / 256), 256>>>(Wp, wp2, wp2 + PWQ, PWQ);
    split2_kernel<<<(int)((PQ2 + 255) / 256), 256>>>(xq, xq2, xq2 + PQ2, PQ2);
    split2_kernel<<<(int)((PK2 + 255) / 256), 256>>>(xkm, xkm2, xkm2 + PK2, PK2);
    mmg<3, 64, 3><<<dim3(CC / 64, MQ / 64, 1), 512, SM_3_64_3>>>(
        xq2, xq2 + PQ2, nullptr, CC, 0,
        wq2, wq2 + PWQ, nullptr, CC, 0, 0,
        qm, CC, 0, nullptr, 1.f, CC, CC, 1, nullptr, 0, nullptr);
    mmg<3, 64, 3><<<dim3(2 * CC / 64, MK / 64, 1), 512, SM_3_64_3>>>(
        xkm2, xkm2 + PK2, nullptr, CC, 0,
        wkv2, wkv2 + PWKV, nullptr, CC, 0, 0,
        kvm, 2 * CC, 0, nullptr, 1.f, 2 * CC, CC, 1, nullptr, 0, nullptr);

    // ---- head prep (padded K=128) ----
    split_qpad_kernel<<<(int)((PQP + 255) / 256), 256>>>(qm, qp2, qp2 + PQP);
    split_kpad_kernel<<<(int)((PKP + 255) / 256), 256>>>(kvm, kp2, kp2 + PKP);
    split_vT_kernel<<<(int)((PVP + 255) / 256), 256>>>(kvm, vp2, vp2 + PVP);

    // ---- attention ----
    float scl = 1.0f / sqrtf((float)HD);
    mmg<3, 64, 3><<<dim3(MK / 64, MQ / 64, HEADS), 512, SM_3_64_3>>>(
        qp2, qp2 + PQP, nullptr, 128, (long)MQ * 128,
        kp2, kp2 + PKP, nullptr, 128, (long)MK * 128, 0,
        S, MK, (long)MQ * MK, nullptr, scl, MK, 128, 1, nullptr, 0, nullptr);
    softmax_b_kernel<<<HEADS * MQ, 256>>>(S, sh, sl);
    mmg<3, 64, 3><<<dim3(2, MQ / 64, HEADS), 512, SM_3_64_3>>>(
        sh, sl, nullptr, MK, (long)MQ * MK,
        vp2, vp2 + PVP, nullptr, MK, (long)HD * MK, 0,
        ao, CC, HD, nullptr, 1.f, HD, MK, 1, nullptr, 0, nullptr);

    // ---- output projection + unmerge ----
    split2_kernel<<<(int)((PQ2 + 255) / 256), 256>>>(ao, ao2, ao2 + PQ2, PQ2);
    mmg<3, 64, 3><<<dim3(CC / 64, MQ / 64, 1), 512, SM_3_64_3>>>(
        ao2, ao2 + PQ2, nullptr, CC, 0,
        wp2, wp2 + PWQ, nullptr, CC, 0, 0,
        proj, CC, 0, bp, 1.f, CC, CC, 1, nullptr, 0, nullptr);
    unmerge_kernel<<<NQ, 256>>>(proj, out, aq, bq, permq, dstq);
}